// round 11
// baseline (speedup 1.0000x reference)
#include <cuda_runtime.h>
#include <cstdint>

#define NNODES 50000
#define NPAD   50048           // 391 * 128
#define NEDGES 800000
#define SCAN_T 1024

// ======================= device-global scratch =======================
__device__ __align__(16) int   g_deg[NNODES];
__device__ __align__(16) int   g_rowptr[NNODES + 1];
__device__ __align__(16) int   g_cursor[NNODES];
__device__ __align__(16) int   g_csr_src[NEDGES];
__device__ __align__(16) float g_inv[NNODES];
__device__ __align__(16) float g_z[NNODES * 256];    // [z_l | z_r] stacked
__device__ __align__(16) float g_h1[NNODES * 128];
__device__ __align__(16) float g_h2[NNODES * 64];
// tf32 hi/lo splits (stored as u32 with low 13 bits zero)
__device__ __align__(16) unsigned int g_xh[NPAD * 128];
__device__ __align__(16) unsigned int g_xl[NPAD * 128];
__device__ __align__(16) unsigned int g_wh[256 * 128];
__device__ __align__(16) unsigned int g_wl[256 * 128];

// SEL: 0 = kernel parameter, 1 = g_h1, 2 = g_h2 (resolved in device code)
template <int SEL>
__device__ __forceinline__ const float* select_src(const float* p) {
    if (SEL == 1) return g_h1;
    if (SEL == 2) return g_h2;
    return p;
}
template <int SEL>
__device__ __forceinline__ float* select_dst(float* p) {
    if (SEL == 1) return g_h1;
    if (SEL == 2) return g_h2;
    return p;
}

// ======================= CSR build =======================
__global__ void zero_deg_kernel() {
    int i = blockIdx.x * blockDim.x + threadIdx.x;
    if (i < NNODES) g_deg[i] = 0;
}
__global__ void count_kernel(const int* __restrict__ ei) {
    int e = blockIdx.x * blockDim.x + threadIdx.x;
    if (e < NEDGES) atomicAdd(&g_deg[ei[NEDGES + e]], 1);
}
__global__ void scan_kernel() {
    __shared__ int partial[SCAN_T];
    const int t = threadIdx.x;
    const int CH = (NNODES + SCAN_T - 1) / SCAN_T;
    const int base = t * CH;
    int s = 0;
    for (int i = 0; i < CH; i++) {
        int idx = base + i;
        if (idx < NNODES) s += g_deg[idx];
    }
    partial[t] = s;
    __syncthreads();
    for (int off = 1; off < SCAN_T; off <<= 1) {
        int add = (t >= off) ? partial[t - off] : 0;
        __syncthreads();
        partial[t] += add;
        __syncthreads();
    }
    int run = (t == 0) ? 0 : partial[t - 1];
    for (int i = 0; i < CH; i++) {
        int idx = base + i;
        if (idx < NNODES) {
            g_rowptr[idx] = run;
            g_cursor[idx] = run;
            g_inv[idx] = 1.0f / fmaxf((float)g_deg[idx], 1.0f);
            run += g_deg[idx];
        }
    }
    if (t == SCAN_T - 1) g_rowptr[NNODES] = partial[SCAN_T - 1];
}
__global__ void fill_kernel(const int* __restrict__ ei) {
    int e = blockIdx.x * blockDim.x + threadIdx.x;
    if (e < NEDGES) {
        int dst = ei[NEDGES + e];
        int slot = atomicAdd(&g_cursor[dst], 1);
        g_csr_src[slot] = ei[e];
    }
}

// ======================= tf32 split conversion =======================
__device__ __forceinline__ void split_tf32(float f, unsigned int& hi, unsigned int& lo) {
    asm("cvt.rna.tf32.f32 %0, %1;" : "=r"(hi) : "f"(f));
    float r = f - __uint_as_float(hi);
    asm("cvt.rna.tf32.f32 %0, %1;" : "=r"(lo) : "f"(r));
}

// x (or h) -> g_xh/g_xl [NPAD x I], pad rows zeroed. 4 floats/thread.
template <int I, int SEL>
__global__ void conv_x_kernel(const float* __restrict__ xp) {
    const float* x = select_src<SEL>(xp);
    int t = blockIdx.x * blockDim.x + threadIdx.x;
    if (t >= NPAD * I / 4) return;
    int row = (t * 4) / I;
    uint4 hi = make_uint4(0, 0, 0, 0), lo = make_uint4(0, 0, 0, 0);
    if (row < NNODES) {
        float4 f = reinterpret_cast<const float4*>(x)[t];
        split_tf32(f.x, hi.x, lo.x);
        split_tf32(f.y, hi.y, lo.y);
        split_tf32(f.z, hi.z, lo.z);
        split_tf32(f.w, hi.w, lo.w);
    }
    reinterpret_cast<uint4*>(g_xh)[t] = hi;
    reinterpret_cast<uint4*>(g_xl)[t] = lo;
}

// W = [Wl;Wr] (2O x I) -> g_wh/g_wl
template <int I, int O>
__global__ void conv_w_kernel(const float* __restrict__ Wl,
                              const float* __restrict__ Wr) {
    int t = blockIdx.x * blockDim.x + threadIdx.x;
    if (t >= 2 * O * I / 4) return;
    int base = t * 4;
    int j = base / I;
    int k = base % I;
    const float* wrow = (j < O) ? (Wl + (size_t)j * I) : (Wr + (size_t)(j - O) * I);
    float4 f = *reinterpret_cast<const float4*>(wrow + k);
    uint4 hi, lo;
    split_tf32(f.x, hi.x, lo.x);
    split_tf32(f.y, hi.y, lo.y);
    split_tf32(f.z, hi.z, lo.z);
    split_tf32(f.w, hi.w, lo.w);
    reinterpret_cast<uint4*>(g_wh)[t] = hi;
    reinterpret_cast<uint4*>(g_wl)[t] = lo;
}

// ======================= split-tf32 mma.sync GEMM =======================
// z[node][j] = x[node] . W[j]  via D = Ah*Bh + Ah*Bl + Al*Bh (fp32 acc).
// Block: 256 thr (8 warps), tile BM=128 x BN=64, BK=16.
// Warp w: rows 16w..16w+15, cols n0..n0+63 (8 m16n8k8 tiles, 32 f32 accs).
// Smem row stride 20 words: fragment LDS conflict-free, STS.128-aligned.
template <int I, int N2>
__global__ __launch_bounds__(256)
void mma_gemm_kernel() {
    __shared__ __align__(16) unsigned int as[128][20];
    __shared__ __align__(16) unsigned int bs[64][20];

    const int t    = threadIdx.x;
    const int w    = t >> 5;
    const int lane = t & 31;
    const int gid  = lane >> 2;   // 0..7
    const int tig  = lane & 3;    // 0..3
    const int m0   = blockIdx.x * 128;
    const int n0   = blockIdx.y * 64;
    const int wrow = w * 16;

    float acc[8][4];
#pragma unroll
    for (int j = 0; j < 8; j++)
#pragma unroll
        for (int c = 0; c < 4; c++) acc[j][c] = 0.0f;

#pragma unroll
    for (int s = 0; s < 3; s++) {
        const unsigned int* A = (s == 2) ? g_xl : g_xh;
        const unsigned int* B = (s == 1) ? g_wl : g_wh;
        for (int k0 = 0; k0 < I; k0 += 16) {
            // A tile: 128 rows x 16 k (512 uint4 over 256 thr)
#pragma unroll
            for (int r = 0; r < 2; r++) {
                int f   = t + r * 256;
                int row = f >> 2;
                int q   = f & 3;
                uint4 v = *reinterpret_cast<const uint4*>(
                    A + (size_t)(m0 + row) * I + k0 + 4 * q);
                *reinterpret_cast<uint4*>(&as[row][4 * q]) = v;
            }
            // B tile: 64 rows x 16 k (256 uint4)
            {
                int row = t >> 2;
                int q   = t & 3;
                uint4 v = *reinterpret_cast<const uint4*>(
                    B + (size_t)(n0 + row) * I + k0 + 4 * q);
                *reinterpret_cast<uint4*>(&bs[row][4 * q]) = v;
            }
            __syncthreads();
#pragma unroll
            for (int ks = 0; ks < 2; ks++) {
                const int kc = 8 * ks;
                unsigned int a0 = as[wrow + gid][kc + tig];
                unsigned int a1 = as[wrow + gid + 8][kc + tig];
                unsigned int a2 = as[wrow + gid][kc + tig + 4];
                unsigned int a3 = as[wrow + gid + 8][kc + tig + 4];
#pragma unroll
                for (int j = 0; j < 8; j++) {
                    unsigned int b0 = bs[8 * j + gid][kc + tig];
                    unsigned int b1 = bs[8 * j + gid][kc + tig + 4];
                    asm volatile(
                        "mma.sync.aligned.m16n8k8.row.col.f32.tf32.tf32.f32 "
                        "{%0,%1,%2,%3}, {%4,%5,%6,%7}, {%8,%9}, {%0,%1,%2,%3};"
                        : "+f"(acc[j][0]), "+f"(acc[j][1]),
                          "+f"(acc[j][2]), "+f"(acc[j][3])
                        : "r"(a0), "r"(a1), "r"(a2), "r"(a3),
                          "r"(b0), "r"(b1));
                }
            }
            __syncthreads();
        }
    }

    // Epilogue: d0,d1 -> (row gid, cols 2tig,2tig+1); d2,d3 -> row gid+8.
    const int node0 = m0 + wrow + gid;
    const int node1 = node0 + 8;
#pragma unroll
    for (int j = 0; j < 8; j++) {
        int col = n0 + 8 * j + 2 * tig;
        if (node0 < NNODES)
            *reinterpret_cast<float2*>(g_z + (size_t)node0 * N2 + col) =
                make_float2(acc[j][0], acc[j][1]);
        if (node1 < NNODES)
            *reinterpret_cast<float2*>(g_z + (size_t)node1 * N2 + col) =
                make_float2(acc[j][2], acc[j][3]);
    }
}

// ======================= gather-add =======================
template <int O, int DSTSEL>
__global__ void gather_add_kernel(const float* __restrict__ b,
                                  float* __restrict__ outp) {
    float* out = select_dst<DSTSEL>(outp);
    int warp = (blockIdx.x * blockDim.x + threadIdx.x) >> 5;
    int lane = threadIdx.x & 31;
    if (warp >= NNODES) return;
    int beg = g_rowptr[warp];
    int end = g_rowptr[warp + 1];
    float inv = g_inv[warp];
    constexpr int RS = 2 * O;

    if (O == 128) {
        float4 acc = make_float4(0.f, 0.f, 0.f, 0.f);
        int j = beg;
        for (; j + 3 < end; j += 4) {
            int s0 = g_csr_src[j], s1 = g_csr_src[j + 1];
            int s2 = g_csr_src[j + 2], s3 = g_csr_src[j + 3];
            float4 v0 = reinterpret_cast<const float4*>(g_z + (size_t)s0 * RS)[lane];
            float4 v1 = reinterpret_cast<const float4*>(g_z + (size_t)s1 * RS)[lane];
            float4 v2 = reinterpret_cast<const float4*>(g_z + (size_t)s2 * RS)[lane];
            float4 v3 = reinterpret_cast<const float4*>(g_z + (size_t)s3 * RS)[lane];
            acc.x += (v0.x + v1.x) + (v2.x + v3.x);
            acc.y += (v0.y + v1.y) + (v2.y + v3.y);
            acc.z += (v0.z + v1.z) + (v2.z + v3.z);
            acc.w += (v0.w + v1.w) + (v2.w + v3.w);
        }
        for (; j < end; j++) {
            int s0 = g_csr_src[j];
            float4 v0 = reinterpret_cast<const float4*>(g_z + (size_t)s0 * RS)[lane];
            acc.x += v0.x; acc.y += v0.y; acc.z += v0.z; acc.w += v0.w;
        }
        float4 zr = reinterpret_cast<const float4*>(g_z + (size_t)warp * RS + O)[lane];
        float4 bb = reinterpret_cast<const float4*>(b)[lane];
        float4 res;
        res.x = acc.x * inv + zr.x + bb.x;
        res.y = acc.y * inv + zr.y + bb.y;
        res.z = acc.z * inv + zr.z + bb.z;
        res.w = acc.w * inv + zr.w + bb.w;
        reinterpret_cast<float4*>(out + (size_t)warp * O)[lane] = res;
    } else {
        float2 acc = make_float2(0.f, 0.f);
        int j = beg;
        for (; j + 3 < end; j += 4) {
            int s0 = g_csr_src[j], s1 = g_csr_src[j + 1];
            int s2 = g_csr_src[j + 2], s3 = g_csr_src[j + 3];
            float2 v0 = reinterpret_cast<const float2*>(g_z + (size_t)s0 * RS)[lane];
            float2 v1 = reinterpret_cast<const float2*>(g_z + (size_t)s1 * RS)[lane];
            float2 v2 = reinterpret_cast<const float2*>(g_z + (size_t)s2 * RS)[lane];
            float2 v3 = reinterpret_cast<const float2*>(g_z + (size_t)s3 * RS)[lane];
            acc.x += (v0.x + v1.x) + (v2.x + v3.x);
            acc.y += (v0.y + v1.y) + (v2.y + v3.y);
        }
        for (; j < end; j++) {
            int s0 = g_csr_src[j];
            float2 v0 = reinterpret_cast<const float2*>(g_z + (size_t)s0 * RS)[lane];
            acc.x += v0.x; acc.y += v0.y;
        }
        float2 zr = reinterpret_cast<const float2*>(g_z + (size_t)warp * RS + O)[lane];
        float2 bb = reinterpret_cast<const float2*>(b)[lane];
        float2 res;
        res.x = acc.x * inv + zr.x + bb.x;
        res.y = acc.y * inv + zr.y + bb.y;
        reinterpret_cast<float2*>(out + (size_t)warp * O)[lane] = res;
    }
}

// ======================= launch =======================
extern "C" void kernel_launch(void* const* d_in, const int* in_sizes, int n_in,
                              void* d_out, int out_size) {
    const float* x   = (const float*)d_in[0];
    const int*   ei  = (const int*)d_in[1];   // int32 (JAX x64 disabled)
    const float* Wl1 = (const float*)d_in[2];
    const float* b1  = (const float*)d_in[3];
    const float* Wr1 = (const float*)d_in[4];
    const float* Wl2 = (const float*)d_in[5];
    const float* b2  = (const float*)d_in[6];
    const float* Wr2 = (const float*)d_in[7];
    const float* Wl3 = (const float*)d_in[8];
    const float* b3  = (const float*)d_in[9];
    const float* Wr3 = (const float*)d_in[10];
    float* out = (float*)d_out;

    const int TB = 256;
    const int MT = NPAD / 128;                    // 391 M-tiles
    const int GW = (NNODES * 32 + TB - 1) / TB;   // gather: warp/node

    // CSR build
    zero_deg_kernel<<<(NNODES + TB - 1) / TB, TB>>>();
    count_kernel<<<(NEDGES + TB - 1) / TB, TB>>>(ei);
    scan_kernel<<<1, SCAN_T>>>();
    fill_kernel<<<(NEDGES + TB - 1) / TB, TB>>>(ei);

    // Layer 1: I=128, N2=256
    conv_x_kernel<128, 0><<<(NPAD * 128 / 4 + TB - 1) / TB, TB>>>(x);
    conv_w_kernel<128, 128><<<(2 * 128 * 128 / 4 + TB - 1) / TB, TB>>>(Wl1, Wr1);
    mma_gemm_kernel<128, 256><<<dim3(MT, 4), 256>>>();
    gather_add_kernel<128, 1><<<GW, TB>>>(b1, nullptr);

    // Layer 2: I=128, N2=128
    conv_x_kernel<128, 1><<<(NPAD * 128 / 4 + TB - 1) / TB, TB>>>(nullptr);
    conv_w_kernel<128, 64><<<(2 * 64 * 128 / 4 + TB - 1) / TB, TB>>>(Wl2, Wr2);
    mma_gemm_kernel<128, 128><<<dim3(MT, 2), 256>>>();
    gather_add_kernel<64, 2><<<GW, TB>>>(b2, nullptr);

    // Layer 3: I=64, N2=256
    conv_x_kernel<64, 2><<<(NPAD * 64 / 4 + TB - 1) / TB, TB>>>(nullptr);
    conv_w_kernel<64, 128><<<(2 * 128 * 64 / 4 + TB - 1) / TB, TB>>>(Wl3, Wr3);
    mma_gemm_kernel<64, 256><<<dim3(MT, 4), 256>>>();
    gather_add_kernel<128, 0><<<GW, TB>>>(b3, out);
}

// round 12
// speedup vs baseline: 1.3756x; 1.3756x over previous
#include <cuda_runtime.h>
#include <cuda_fp16.h>
#include <cstdint>

#define NNODES 50000
#define NPAD   50048           // 391 * 128
#define NEDGES 800000
#define SCAN_T 1024

// ======================= device-global scratch =======================
__device__ __align__(16) int   g_deg[NNODES];
__device__ __align__(16) int   g_rowptr[NNODES + 1];
__device__ __align__(16) int   g_cursor[NNODES];
__device__ __align__(16) int   g_csr_src[NEDGES];
__device__ __align__(16) float g_inv[NNODES];
__device__ __align__(16) float g_z[NNODES * 256];    // [z_l | z_r] stacked
__device__ __align__(16) float g_h1[NNODES * 128];
__device__ __align__(16) float g_h2[NNODES * 64];
// fp16 hi/lo splits (ushort storage)
__device__ __align__(16) unsigned short g_xh[NPAD * 128];
__device__ __align__(16) unsigned short g_xl[NPAD * 128];
__device__ __align__(16) unsigned short g_wh[256 * 128];
__device__ __align__(16) unsigned short g_wl[256 * 128];

// SEL: 0 = kernel parameter, 1 = g_h1, 2 = g_h2 (resolved in device code)
template <int SEL>
__device__ __forceinline__ const float* select_src(const float* p) {
    if (SEL == 1) return g_h1;
    if (SEL == 2) return g_h2;
    return p;
}
template <int SEL>
__device__ __forceinline__ float* select_dst(float* p) {
    if (SEL == 1) return g_h1;
    if (SEL == 2) return g_h2;
    return p;
}

// ======================= CSR build =======================
__global__ void zero_deg_kernel() {
    int i = blockIdx.x * blockDim.x + threadIdx.x;
    if (i < NNODES) g_deg[i] = 0;
}
__global__ void count_kernel(const int* __restrict__ ei) {
    int e = blockIdx.x * blockDim.x + threadIdx.x;
    if (e < NEDGES) atomicAdd(&g_deg[ei[NEDGES + e]], 1);
}
__global__ void scan_kernel() {
    __shared__ int partial[SCAN_T];
    const int t = threadIdx.x;
    const int CH = (NNODES + SCAN_T - 1) / SCAN_T;
    const int base = t * CH;
    int s = 0;
    for (int i = 0; i < CH; i++) {
        int idx = base + i;
        if (idx < NNODES) s += g_deg[idx];
    }
    partial[t] = s;
    __syncthreads();
    for (int off = 1; off < SCAN_T; off <<= 1) {
        int add = (t >= off) ? partial[t - off] : 0;
        __syncthreads();
        partial[t] += add;
        __syncthreads();
    }
    int run = (t == 0) ? 0 : partial[t - 1];
    for (int i = 0; i < CH; i++) {
        int idx = base + i;
        if (idx < NNODES) {
            g_rowptr[idx] = run;
            g_cursor[idx] = run;
            g_inv[idx] = 1.0f / fmaxf((float)g_deg[idx], 1.0f);
            run += g_deg[idx];
        }
    }
    if (t == SCAN_T - 1) g_rowptr[NNODES] = partial[SCAN_T - 1];
}
__global__ void fill_kernel(const int* __restrict__ ei) {
    int e = blockIdx.x * blockDim.x + threadIdx.x;
    if (e < NEDGES) {
        int dst = ei[NEDGES + e];
        int slot = atomicAdd(&g_cursor[dst], 1);
        g_csr_src[slot] = ei[e];
    }
}

// ======================= fp16 split conversion =======================
union U4H8 { uint4 v; unsigned short u16[8]; };

__device__ __forceinline__ void split_f16(float f, unsigned short& hi, unsigned short& lo) {
    __half h = __float2half_rn(f);
    hi = __half_as_ushort(h);
    __half l = __float2half_rn(f - __half2float(h));
    lo = __half_as_ushort(l);
}

// x (or h) -> g_xh/g_xl [NPAD x I], pad rows zeroed. 8 floats/thread.
template <int I, int SEL>
__global__ void conv_x_kernel(const float* __restrict__ xp) {
    const float* x = select_src<SEL>(xp);
    int t = blockIdx.x * blockDim.x + threadIdx.x;
    if (t >= NPAD * I / 8) return;
    int base = t * 8;
    int row = base / I;
    U4H8 hi, lo;
    hi.v = make_uint4(0, 0, 0, 0);
    lo.v = make_uint4(0, 0, 0, 0);
    if (row < NNODES) {
        const float4* src = reinterpret_cast<const float4*>(x + base);
        float4 f0 = src[0], f1 = src[1];
        float f[8] = {f0.x, f0.y, f0.z, f0.w, f1.x, f1.y, f1.z, f1.w};
#pragma unroll
        for (int i = 0; i < 8; i++) split_f16(f[i], hi.u16[i], lo.u16[i]);
    }
    reinterpret_cast<uint4*>(g_xh)[t] = hi.v;
    reinterpret_cast<uint4*>(g_xl)[t] = lo.v;
}

// W = [Wl;Wr] (2O x I) -> g_wh/g_wl
template <int I, int O>
__global__ void conv_w_kernel(const float* __restrict__ Wl,
                              const float* __restrict__ Wr) {
    int t = blockIdx.x * blockDim.x + threadIdx.x;
    if (t >= 2 * O * I / 8) return;
    int base = t * 8;
    int j = base / I;
    int k = base % I;
    const float* wrow = (j < O) ? (Wl + (size_t)j * I) : (Wr + (size_t)(j - O) * I);
    const float4* src = reinterpret_cast<const float4*>(wrow + k);
    float4 f0 = src[0], f1 = src[1];
    float f[8] = {f0.x, f0.y, f0.z, f0.w, f1.x, f1.y, f1.z, f1.w};
    U4H8 hi, lo;
#pragma unroll
    for (int i = 0; i < 8; i++) split_f16(f[i], hi.u16[i], lo.u16[i]);
    reinterpret_cast<uint4*>(g_wh)[t] = hi.v;
    reinterpret_cast<uint4*>(g_wl)[t] = lo.v;
}

// ======================= split-fp16 mma.sync GEMM =======================
// z = x @ W^T via D = Ah*Bh + Ah*Bl + Al*Bh (fp32 acc), m16n8k16.
// Block: 256 thr (8 warps), BM=128 x BN=64, K-chunk=16 (one mma-K per chunk).
// Warp w: rows 16w..16w+15, cols n0..63. All 4 tiles loaded ONCE per chunk;
// 3 combos issued per fragment set. Smem u32-stride 12: conflict-free frags.
template <int I, int N2>
__global__ __launch_bounds__(256)
void mma_gemm_kernel() {
    __shared__ __align__(16) unsigned int ash[128][12];
    __shared__ __align__(16) unsigned int asl[128][12];
    __shared__ __align__(16) unsigned int bsh[64][12];
    __shared__ __align__(16) unsigned int bsl[64][12];

    const int t    = threadIdx.x;
    const int w    = t >> 5;
    const int lane = t & 31;
    const int gid  = lane >> 2;   // 0..7
    const int tig  = lane & 3;    // 0..3
    const int m0   = blockIdx.x * 128;
    const int n0   = blockIdx.y * 64;
    const int wrow = w * 16;

    float acc[8][4];
#pragma unroll
    for (int j = 0; j < 8; j++)
#pragma unroll
        for (int c = 0; c < 4; c++) acc[j][c] = 0.0f;

    // A tile-load coords: 128 rows x 2 uint4 (16 halves) -> 256 threads
    const int arow = t >> 1, aq = t & 1;
    // B tile-load coords: 64 rows x 2 uint4, hi for t<128 / lo for t>=128
    const int tb = t & 127;
    const int brow = tb >> 1, bq = tb & 1;

    for (int k0 = 0; k0 < I; k0 += 16) {
        {
            uint4 vh = *reinterpret_cast<const uint4*>(
                g_xh + (size_t)(m0 + arow) * I + k0 + 8 * aq);
            uint4 vl = *reinterpret_cast<const uint4*>(
                g_xl + (size_t)(m0 + arow) * I + k0 + 8 * aq);
            *reinterpret_cast<uint4*>(&ash[arow][4 * aq]) = vh;
            *reinterpret_cast<uint4*>(&asl[arow][4 * aq]) = vl;
            const unsigned short* W = (t < 128) ? g_wh : g_wl;
            uint4 vb = *reinterpret_cast<const uint4*>(
                W + (size_t)(n0 + brow) * I + k0 + 8 * bq);
            if (t < 128)
                *reinterpret_cast<uint4*>(&bsh[brow][4 * bq]) = vb;
            else
                *reinterpret_cast<uint4*>(&bsl[brow][4 * bq]) = vb;
        }
        __syncthreads();
        {
            unsigned int ah0 = ash[wrow + gid][tig];
            unsigned int ah1 = ash[wrow + gid + 8][tig];
            unsigned int ah2 = ash[wrow + gid][tig + 4];
            unsigned int ah3 = ash[wrow + gid + 8][tig + 4];
            unsigned int al0 = asl[wrow + gid][tig];
            unsigned int al1 = asl[wrow + gid + 8][tig];
            unsigned int al2 = asl[wrow + gid][tig + 4];
            unsigned int al3 = asl[wrow + gid + 8][tig + 4];
#pragma unroll
            for (int j = 0; j < 8; j++) {
                unsigned int bh0 = bsh[8 * j + gid][tig];
                unsigned int bh1 = bsh[8 * j + gid][tig + 4];
                unsigned int bl0 = bsl[8 * j + gid][tig];
                unsigned int bl1 = bsl[8 * j + gid][tig + 4];
                asm volatile(
                    "mma.sync.aligned.m16n8k16.row.col.f32.f16.f16.f32 "
                    "{%0,%1,%2,%3}, {%4,%5,%6,%7}, {%8,%9}, {%0,%1,%2,%3};"
                    : "+f"(acc[j][0]), "+f"(acc[j][1]),
                      "+f"(acc[j][2]), "+f"(acc[j][3])
                    : "r"(ah0), "r"(ah1), "r"(ah2), "r"(ah3), "r"(bh0), "r"(bh1));
                asm volatile(
                    "mma.sync.aligned.m16n8k16.row.col.f32.f16.f16.f32 "
                    "{%0,%1,%2,%3}, {%4,%5,%6,%7}, {%8,%9}, {%0,%1,%2,%3};"
                    : "+f"(acc[j][0]), "+f"(acc[j][1]),
                      "+f"(acc[j][2]), "+f"(acc[j][3])
                    : "r"(ah0), "r"(ah1), "r"(ah2), "r"(ah3), "r"(bl0), "r"(bl1));
                asm volatile(
                    "mma.sync.aligned.m16n8k16.row.col.f32.f16.f16.f32 "
                    "{%0,%1,%2,%3}, {%4,%5,%6,%7}, {%8,%9}, {%0,%1,%2,%3};"
                    : "+f"(acc[j][0]), "+f"(acc[j][1]),
                      "+f"(acc[j][2]), "+f"(acc[j][3])
                    : "r"(al0), "r"(al1), "r"(al2), "r"(al3), "r"(bh0), "r"(bh1));
            }
        }
        __syncthreads();
    }

    // Epilogue: c0,c1 -> (row gid, cols 2tig,2tig+1); c2,c3 -> row gid+8.
    const int node0 = m0 + wrow + gid;
    const int node1 = node0 + 8;
#pragma unroll
    for (int j = 0; j < 8; j++) {
        int col = n0 + 8 * j + 2 * tig;
        if (node0 < NNODES)
            *reinterpret_cast<float2*>(g_z + (size_t)node0 * N2 + col) =
                make_float2(acc[j][0], acc[j][1]);
        if (node1 < NNODES)
            *reinterpret_cast<float2*>(g_z + (size_t)node1 * N2 + col) =
                make_float2(acc[j][2], acc[j][3]);
    }
}

// ======================= gather-add =======================
template <int O, int DSTSEL>
__global__ void gather_add_kernel(const float* __restrict__ b,
                                  float* __restrict__ outp) {
    float* out = select_dst<DSTSEL>(outp);
    int warp = (blockIdx.x * blockDim.x + threadIdx.x) >> 5;
    int lane = threadIdx.x & 31;
    if (warp >= NNODES) return;
    int beg = g_rowptr[warp];
    int end = g_rowptr[warp + 1];
    float inv = g_inv[warp];
    constexpr int RS = 2 * O;

    if (O == 128) {
        float4 acc = make_float4(0.f, 0.f, 0.f, 0.f);
        int j = beg;
        for (; j + 3 < end; j += 4) {
            int s0 = g_csr_src[j], s1 = g_csr_src[j + 1];
            int s2 = g_csr_src[j + 2], s3 = g_csr_src[j + 3];
            float4 v0 = reinterpret_cast<const float4*>(g_z + (size_t)s0 * RS)[lane];
            float4 v1 = reinterpret_cast<const float4*>(g_z + (size_t)s1 * RS)[lane];
            float4 v2 = reinterpret_cast<const float4*>(g_z + (size_t)s2 * RS)[lane];
            float4 v3 = reinterpret_cast<const float4*>(g_z + (size_t)s3 * RS)[lane];
            acc.x += (v0.x + v1.x) + (v2.x + v3.x);
            acc.y += (v0.y + v1.y) + (v2.y + v3.y);
            acc.z += (v0.z + v1.z) + (v2.z + v3.z);
            acc.w += (v0.w + v1.w) + (v2.w + v3.w);
        }
        for (; j < end; j++) {
            int s0 = g_csr_src[j];
            float4 v0 = reinterpret_cast<const float4*>(g_z + (size_t)s0 * RS)[lane];
            acc.x += v0.x; acc.y += v0.y; acc.z += v0.z; acc.w += v0.w;
        }
        float4 zr = reinterpret_cast<const float4*>(g_z + (size_t)warp * RS + O)[lane];
        float4 bb = reinterpret_cast<const float4*>(b)[lane];
        float4 res;
        res.x = acc.x * inv + zr.x + bb.x;
        res.y = acc.y * inv + zr.y + bb.y;
        res.z = acc.z * inv + zr.z + bb.z;
        res.w = acc.w * inv + zr.w + bb.w;
        reinterpret_cast<float4*>(out + (size_t)warp * O)[lane] = res;
    } else {
        float2 acc = make_float2(0.f, 0.f);
        int j = beg;
        for (; j + 3 < end; j += 4) {
            int s0 = g_csr_src[j], s1 = g_csr_src[j + 1];
            int s2 = g_csr_src[j + 2], s3 = g_csr_src[j + 3];
            float2 v0 = reinterpret_cast<const float2*>(g_z + (size_t)s0 * RS)[lane];
            float2 v1 = reinterpret_cast<const float2*>(g_z + (size_t)s1 * RS)[lane];
            float2 v2 = reinterpret_cast<const float2*>(g_z + (size_t)s2 * RS)[lane];
            float2 v3 = reinterpret_cast<const float2*>(g_z + (size_t)s3 * RS)[lane];
            acc.x += (v0.x + v1.x) + (v2.x + v3.x);
            acc.y += (v0.y + v1.y) + (v2.y + v3.y);
        }
        for (; j < end; j++) {
            int s0 = g_csr_src[j];
            float2 v0 = reinterpret_cast<const float2*>(g_z + (size_t)s0 * RS)[lane];
            acc.x += v0.x; acc.y += v0.y;
        }
        float2 zr = reinterpret_cast<const float2*>(g_z + (size_t)warp * RS + O)[lane];
        float2 bb = reinterpret_cast<const float2*>(b)[lane];
        float2 res;
        res.x = acc.x * inv + zr.x + bb.x;
        res.y = acc.y * inv + zr.y + bb.y;
        reinterpret_cast<float2*>(out + (size_t)warp * O)[lane] = res;
    }
}

// ======================= launch =======================
extern "C" void kernel_launch(void* const* d_in, const int* in_sizes, int n_in,
                              void* d_out, int out_size) {
    const float* x   = (const float*)d_in[0];
    const int*   ei  = (const int*)d_in[1];   // int32 (JAX x64 disabled)
    const float* Wl1 = (const float*)d_in[2];
    const float* b1  = (const float*)d_in[3];
    const float* Wr1 = (const float*)d_in[4];
    const float* Wl2 = (const float*)d_in[5];
    const float* b2  = (const float*)d_in[6];
    const float* Wr2 = (const float*)d_in[7];
    const float* Wl3 = (const float*)d_in[8];
    const float* b3  = (const float*)d_in[9];
    const float* Wr3 = (const float*)d_in[10];
    float* out = (float*)d_out;

    const int TB = 256;
    const int MT = NPAD / 128;                    // 391 M-tiles
    const int GW = (NNODES * 32 + TB - 1) / TB;   // gather: warp/node

    // CSR build
    zero_deg_kernel<<<(NNODES + TB - 1) / TB, TB>>>();
    count_kernel<<<(NEDGES + TB - 1) / TB, TB>>>(ei);
    scan_kernel<<<1, SCAN_T>>>();
    fill_kernel<<<(NEDGES + TB - 1) / TB, TB>>>(ei);

    // Layer 1: I=128, N2=256
    conv_x_kernel<128, 0><<<(NPAD * 128 / 8 + TB - 1) / TB, TB>>>(x);
    conv_w_kernel<128, 128><<<(2 * 128 * 128 / 8 + TB - 1) / TB, TB>>>(Wl1, Wr1);
    mma_gemm_kernel<128, 256><<<dim3(MT, 4), 256>>>();
    gather_add_kernel<128, 1><<<GW, TB>>>(b1, nullptr);

    // Layer 2: I=128, N2=128
    conv_x_kernel<128, 1><<<(NPAD * 128 / 8 + TB - 1) / TB, TB>>>(nullptr);
    conv_w_kernel<128, 64><<<(2 * 64 * 128 / 8 + TB - 1) / TB, TB>>>(Wl2, Wr2);
    mma_gemm_kernel<128, 128><<<dim3(MT, 2), 256>>>();
    gather_add_kernel<64, 2><<<GW, TB>>>(b2, nullptr);

    // Layer 3: I=64, N2=256
    conv_x_kernel<64, 2><<<(NPAD * 64 / 8 + TB - 1) / TB, TB>>>(nullptr);
    conv_w_kernel<64, 128><<<(2 * 128 * 64 / 8 + TB - 1) / TB, TB>>>(Wl3, Wr3);
    mma_gemm_kernel<64, 256><<<dim3(MT, 4), 256>>>();
    gather_add_kernel<128, 0><<<GW, TB>>>(b3, out);
}

// round 13
// speedup vs baseline: 1.4285x; 1.0384x over previous
#include <cuda_runtime.h>
#include <cuda_fp16.h>
#include <cstdint>

#define NNODES 50000
#define NPAD   50048           // 391 * 128
#define NEDGES 800000
#define SCAN_T 1024

// ======================= device-global scratch =======================
__device__ __align__(16) int   g_deg[NNODES];
__device__ __align__(16) int   g_rowptr[NNODES + 1];
__device__ __align__(16) int   g_cursor[NNODES];
__device__ __align__(16) int   g_csr_src[NEDGES];
__device__ __align__(16) float g_inv[NNODES];
__device__ __align__(16) float g_z[NNODES * 256];    // [z_l | z_r] stacked
// fp16 hi/lo splits (ushort storage); layout [NPAD x I] for current layer
__device__ __align__(16) unsigned short g_xh[NPAD * 128];
__device__ __align__(16) unsigned short g_xl[NPAD * 128];
__device__ __align__(16) unsigned short g_wh[256 * 128];
__device__ __align__(16) unsigned short g_wl[256 * 128];

// ======================= CSR build =======================
__global__ void zero_deg_kernel() {
    int i = blockIdx.x * blockDim.x + threadIdx.x;
    if (i < NNODES) g_deg[i] = 0;
}
__global__ void count_kernel(const int* __restrict__ ei) {
    int e = blockIdx.x * blockDim.x + threadIdx.x;
    if (e < NEDGES) atomicAdd(&g_deg[ei[NEDGES + e]], 1);
}
__global__ void scan_kernel() {
    __shared__ int partial[SCAN_T];
    const int t = threadIdx.x;
    const int CH = (NNODES + SCAN_T - 1) / SCAN_T;
    const int base = t * CH;
    int s = 0;
    for (int i = 0; i < CH; i++) {
        int idx = base + i;
        if (idx < NNODES) s += g_deg[idx];
    }
    partial[t] = s;
    __syncthreads();
    for (int off = 1; off < SCAN_T; off <<= 1) {
        int add = (t >= off) ? partial[t - off] : 0;
        __syncthreads();
        partial[t] += add;
        __syncthreads();
    }
    int run = (t == 0) ? 0 : partial[t - 1];
    for (int i = 0; i < CH; i++) {
        int idx = base + i;
        if (idx < NNODES) {
            g_rowptr[idx] = run;
            g_cursor[idx] = run;
            g_inv[idx] = 1.0f / fmaxf((float)g_deg[idx], 1.0f);
            run += g_deg[idx];
        }
    }
    if (t == SCAN_T - 1) g_rowptr[NNODES] = partial[SCAN_T - 1];
}
__global__ void fill_kernel(const int* __restrict__ ei) {
    int e = blockIdx.x * blockDim.x + threadIdx.x;
    if (e < NEDGES) {
        int dst = ei[NEDGES + e];
        int slot = atomicAdd(&g_cursor[dst], 1);
        g_csr_src[slot] = ei[e];
    }
}

// ======================= fp16 split helpers =======================
union U4H8 { uint4 v; unsigned short u16[8]; };

__device__ __forceinline__ void split_f16(float f, unsigned short& hi, unsigned short& lo) {
    __half h = __float2half_rn(f);
    hi = __half_as_ushort(h);
    __half l = __float2half_rn(f - __half2float(h));
    lo = __half_as_ushort(l);
}

// x (input param only) -> g_xh/g_xl [NPAD x I], pad rows zeroed.
template <int I>
__global__ void conv_x_kernel(const float* __restrict__ x) {
    int t = blockIdx.x * blockDim.x + threadIdx.x;
    if (t >= NPAD * I / 8) return;
    int base = t * 8;
    int row = base / I;
    U4H8 hi, lo;
    hi.v = make_uint4(0, 0, 0, 0);
    lo.v = make_uint4(0, 0, 0, 0);
    if (row < NNODES) {
        const float4* src = reinterpret_cast<const float4*>(x + base);
        float4 f0 = src[0], f1 = src[1];
        float f[8] = {f0.x, f0.y, f0.z, f0.w, f1.x, f1.y, f1.z, f1.w};
#pragma unroll
        for (int i = 0; i < 8; i++) split_f16(f[i], hi.u16[i], lo.u16[i]);
    }
    reinterpret_cast<uint4*>(g_xh)[t] = hi.v;
    reinterpret_cast<uint4*>(g_xl)[t] = lo.v;
}

// Zero padding rows NNODES..NPAD-1 of g_xh/g_xl for layout width I.
template <int I>
__global__ void zero_pad_kernel() {
    int t = blockIdx.x * blockDim.x + threadIdx.x;
    constexpr int NE = (NPAD - NNODES) * I / 8;   // uint4 count
    if (t >= NE) return;
    reinterpret_cast<uint4*>(g_xh + (size_t)NNODES * I)[t] = make_uint4(0, 0, 0, 0);
    reinterpret_cast<uint4*>(g_xl + (size_t)NNODES * I)[t] = make_uint4(0, 0, 0, 0);
}

// W = [Wl;Wr] (2O x I) -> g_wh/g_wl
template <int I, int O>
__global__ void conv_w_kernel(const float* __restrict__ Wl,
                              const float* __restrict__ Wr) {
    int t = blockIdx.x * blockDim.x + threadIdx.x;
    if (t >= 2 * O * I / 8) return;
    int base = t * 8;
    int j = base / I;
    int k = base % I;
    const float* wrow = (j < O) ? (Wl + (size_t)j * I) : (Wr + (size_t)(j - O) * I);
    const float4* src = reinterpret_cast<const float4*>(wrow + k);
    float4 f0 = src[0], f1 = src[1];
    float f[8] = {f0.x, f0.y, f0.z, f0.w, f1.x, f1.y, f1.z, f1.w};
    U4H8 hi, lo;
#pragma unroll
    for (int i = 0; i < 8; i++) split_f16(f[i], hi.u16[i], lo.u16[i]);
    reinterpret_cast<uint4*>(g_wh)[t] = hi.v;
    reinterpret_cast<uint4*>(g_wl)[t] = lo.v;
}

// ======================= split-fp16 mma.sync GEMM =======================
// z = x @ W^T via D = Ah*Bh + Ah*Bl + Al*Bh (fp32 acc), m16n8k16.
// Block: 256 thr (8 warps), BM=128 x BN=64, K-chunk=16.
template <int I, int N2>
__global__ __launch_bounds__(256)
void mma_gemm_kernel() {
    __shared__ __align__(16) unsigned int ash[128][12];
    __shared__ __align__(16) unsigned int asl[128][12];
    __shared__ __align__(16) unsigned int bsh[64][12];
    __shared__ __align__(16) unsigned int bsl[64][12];

    const int t    = threadIdx.x;
    const int w    = t >> 5;
    const int lane = t & 31;
    const int gid  = lane >> 2;
    const int tig  = lane & 3;
    const int m0   = blockIdx.x * 128;
    const int n0   = blockIdx.y * 64;
    const int wrow = w * 16;

    float acc[8][4];
#pragma unroll
    for (int j = 0; j < 8; j++)
#pragma unroll
        for (int c = 0; c < 4; c++) acc[j][c] = 0.0f;

    const int arow = t >> 1, aq = t & 1;
    const int tb = t & 127;
    const int brow = tb >> 1, bq = tb & 1;

    for (int k0 = 0; k0 < I; k0 += 16) {
        {
            uint4 vh = *reinterpret_cast<const uint4*>(
                g_xh + (size_t)(m0 + arow) * I + k0 + 8 * aq);
            uint4 vl = *reinterpret_cast<const uint4*>(
                g_xl + (size_t)(m0 + arow) * I + k0 + 8 * aq);
            *reinterpret_cast<uint4*>(&ash[arow][4 * aq]) = vh;
            *reinterpret_cast<uint4*>(&asl[arow][4 * aq]) = vl;
            const unsigned short* W = (t < 128) ? g_wh : g_wl;
            uint4 vb = *reinterpret_cast<const uint4*>(
                W + (size_t)(n0 + brow) * I + k0 + 8 * bq);
            if (t < 128)
                *reinterpret_cast<uint4*>(&bsh[brow][4 * bq]) = vb;
            else
                *reinterpret_cast<uint4*>(&bsl[brow][4 * bq]) = vb;
        }
        __syncthreads();
        {
            unsigned int ah0 = ash[wrow + gid][tig];
            unsigned int ah1 = ash[wrow + gid + 8][tig];
            unsigned int ah2 = ash[wrow + gid][tig + 4];
            unsigned int ah3 = ash[wrow + gid + 8][tig + 4];
            unsigned int al0 = asl[wrow + gid][tig];
            unsigned int al1 = asl[wrow + gid + 8][tig];
            unsigned int al2 = asl[wrow + gid][tig + 4];
            unsigned int al3 = asl[wrow + gid + 8][tig + 4];
#pragma unroll
            for (int j = 0; j < 8; j++) {
                unsigned int bh0 = bsh[8 * j + gid][tig];
                unsigned int bh1 = bsh[8 * j + gid][tig + 4];
                unsigned int bl0 = bsl[8 * j + gid][tig];
                unsigned int bl1 = bsl[8 * j + gid][tig + 4];
                asm volatile(
                    "mma.sync.aligned.m16n8k16.row.col.f32.f16.f16.f32 "
                    "{%0,%1,%2,%3}, {%4,%5,%6,%7}, {%8,%9}, {%0,%1,%2,%3};"
                    : "+f"(acc[j][0]), "+f"(acc[j][1]),
                      "+f"(acc[j][2]), "+f"(acc[j][3])
                    : "r"(ah0), "r"(ah1), "r"(ah2), "r"(ah3), "r"(bh0), "r"(bh1));
                asm volatile(
                    "mma.sync.aligned.m16n8k16.row.col.f32.f16.f16.f32 "
                    "{%0,%1,%2,%3}, {%4,%5,%6,%7}, {%8,%9}, {%0,%1,%2,%3};"
                    : "+f"(acc[j][0]), "+f"(acc[j][1]),
                      "+f"(acc[j][2]), "+f"(acc[j][3])
                    : "r"(ah0), "r"(ah1), "r"(ah2), "r"(ah3), "r"(bl0), "r"(bl1));
                asm volatile(
                    "mma.sync.aligned.m16n8k16.row.col.f32.f16.f16.f32 "
                    "{%0,%1,%2,%3}, {%4,%5,%6,%7}, {%8,%9}, {%0,%1,%2,%3};"
                    : "+f"(acc[j][0]), "+f"(acc[j][1]),
                      "+f"(acc[j][2]), "+f"(acc[j][3])
                    : "r"(al0), "r"(al1), "r"(al2), "r"(al3), "r"(bh0), "r"(bh1));
            }
        }
        __syncthreads();
    }

    const int node0 = m0 + wrow + gid;
    const int node1 = node0 + 8;
#pragma unroll
    for (int j = 0; j < 8; j++) {
        int col = n0 + 8 * j + 2 * tig;
        if (node0 < NNODES)
            *reinterpret_cast<float2*>(g_z + (size_t)node0 * N2 + col) =
                make_float2(acc[j][0], acc[j][1]);
        if (node1 < NNODES)
            *reinterpret_cast<float2*>(g_z + (size_t)node1 * N2 + col) =
                make_float2(acc[j][2], acc[j][3]);
    }
}

// ======================= gather-add (fused fp16-split output) =======================
// MODE 0: write f32 to outp. MODE 1: split result to fp16 hi/lo -> g_xh/g_xl
// (becomes next layer's mma input; layout [node][O]).
template <int O, int MODE>
__global__ void gather_add_kernel(const float* __restrict__ b,
                                  float* __restrict__ outp) {
    int warp = (blockIdx.x * blockDim.x + threadIdx.x) >> 5;
    int lane = threadIdx.x & 31;
    if (warp >= NNODES) return;
    int beg = g_rowptr[warp];
    int end = g_rowptr[warp + 1];
    float inv = g_inv[warp];
    constexpr int RS = 2 * O;

    if (O == 128) {
        float4 acc = make_float4(0.f, 0.f, 0.f, 0.f);
        int j = beg;
        for (; j + 3 < end; j += 4) {
            int s0 = g_csr_src[j], s1 = g_csr_src[j + 1];
            int s2 = g_csr_src[j + 2], s3 = g_csr_src[j + 3];
            float4 v0 = reinterpret_cast<const float4*>(g_z + (size_t)s0 * RS)[lane];
            float4 v1 = reinterpret_cast<const float4*>(g_z + (size_t)s1 * RS)[lane];
            float4 v2 = reinterpret_cast<const float4*>(g_z + (size_t)s2 * RS)[lane];
            float4 v3 = reinterpret_cast<const float4*>(g_z + (size_t)s3 * RS)[lane];
            acc.x += (v0.x + v1.x) + (v2.x + v3.x);
            acc.y += (v0.y + v1.y) + (v2.y + v3.y);
            acc.z += (v0.z + v1.z) + (v2.z + v3.z);
            acc.w += (v0.w + v1.w) + (v2.w + v3.w);
        }
        for (; j < end; j++) {
            int s0 = g_csr_src[j];
            float4 v0 = reinterpret_cast<const float4*>(g_z + (size_t)s0 * RS)[lane];
            acc.x += v0.x; acc.y += v0.y; acc.z += v0.z; acc.w += v0.w;
        }
        float4 zr = reinterpret_cast<const float4*>(g_z + (size_t)warp * RS + O)[lane];
        float4 bb = reinterpret_cast<const float4*>(b)[lane];
        float4 res;
        res.x = acc.x * inv + zr.x + bb.x;
        res.y = acc.y * inv + zr.y + bb.y;
        res.z = acc.z * inv + zr.z + bb.z;
        res.w = acc.w * inv + zr.w + bb.w;
        if (MODE == 0) {
            reinterpret_cast<float4*>(outp + (size_t)warp * O)[lane] = res;
        } else {
            unsigned short h[4], l[4];
            split_f16(res.x, h[0], l[0]);
            split_f16(res.y, h[1], l[1]);
            split_f16(res.z, h[2], l[2]);
            split_f16(res.w, h[3], l[3]);
            reinterpret_cast<uint2*>(g_xh + (size_t)warp * O)[lane] =
                *reinterpret_cast<uint2*>(h);
            reinterpret_cast<uint2*>(g_xl + (size_t)warp * O)[lane] =
                *reinterpret_cast<uint2*>(l);
        }
    } else {
        float2 acc = make_float2(0.f, 0.f);
        int j = beg;
        for (; j + 3 < end; j += 4) {
            int s0 = g_csr_src[j], s1 = g_csr_src[j + 1];
            int s2 = g_csr_src[j + 2], s3 = g_csr_src[j + 3];
            float2 v0 = reinterpret_cast<const float2*>(g_z + (size_t)s0 * RS)[lane];
            float2 v1 = reinterpret_cast<const float2*>(g_z + (size_t)s1 * RS)[lane];
            float2 v2 = reinterpret_cast<const float2*>(g_z + (size_t)s2 * RS)[lane];
            float2 v3 = reinterpret_cast<const float2*>(g_z + (size_t)s3 * RS)[lane];
            acc.x += (v0.x + v1.x) + (v2.x + v3.x);
            acc.y += (v0.y + v1.y) + (v2.y + v3.y);
        }
        for (; j < end; j++) {
            int s0 = g_csr_src[j];
            float2 v0 = reinterpret_cast<const float2*>(g_z + (size_t)s0 * RS)[lane];
            acc.x += v0.x; acc.y += v0.y;
        }
        float2 zr = reinterpret_cast<const float2*>(g_z + (size_t)warp * RS + O)[lane];
        float2 bb = reinterpret_cast<const float2*>(b)[lane];
        float2 res;
        res.x = acc.x * inv + zr.x + bb.x;
        res.y = acc.y * inv + zr.y + bb.y;
        if (MODE == 0) {
            reinterpret_cast<float2*>(outp + (size_t)warp * O)[lane] = res;
        } else {
            unsigned short h[2], l[2];
            split_f16(res.x, h[0], l[0]);
            split_f16(res.y, h[1], l[1]);
            reinterpret_cast<unsigned int*>(g_xh + (size_t)warp * O)[lane] =
                *reinterpret_cast<unsigned int*>(h);
            reinterpret_cast<unsigned int*>(g_xl + (size_t)warp * O)[lane] =
                *reinterpret_cast<unsigned int*>(l);
        }
    }
}

// ======================= launch =======================
extern "C" void kernel_launch(void* const* d_in, const int* in_sizes, int n_in,
                              void* d_out, int out_size) {
    const float* x   = (const float*)d_in[0];
    const int*   ei  = (const int*)d_in[1];   // int32 (JAX x64 disabled)
    const float* Wl1 = (const float*)d_in[2];
    const float* b1  = (const float*)d_in[3];
    const float* Wr1 = (const float*)d_in[4];
    const float* Wl2 = (const float*)d_in[5];
    const float* b2  = (const float*)d_in[6];
    const float* Wr2 = (const float*)d_in[7];
    const float* Wl3 = (const float*)d_in[8];
    const float* b3  = (const float*)d_in[9];
    const float* Wr3 = (const float*)d_in[10];
    float* out = (float*)d_out;

    const int TB = 256;
    const int MT = NPAD / 128;                    // 391 M-tiles
    const int GW = (NNODES * 32 + TB - 1) / TB;   // gather: warp/node

    // CSR build
    zero_deg_kernel<<<(NNODES + TB - 1) / TB, TB>>>();
    count_kernel<<<(NEDGES + TB - 1) / TB, TB>>>(ei);
    scan_kernel<<<1, SCAN_T>>>();
    fill_kernel<<<(NEDGES + TB - 1) / TB, TB>>>(ei);

    // Layer 1: I=128, N2=256 (x from input; conv_x zeroes pad rows)
    conv_x_kernel<128><<<(NPAD * 128 / 8 + TB - 1) / TB, TB>>>(x);
    conv_w_kernel<128, 128><<<(2 * 128 * 128 / 8 + TB - 1) / TB, TB>>>(Wl1, Wr1);
    mma_gemm_kernel<128, 256><<<dim3(MT, 4), 256>>>();
    gather_add_kernel<128, 1><<<GW, TB>>>(b1, nullptr);   // -> g_xh/g_xl [n][128]
    zero_pad_kernel<128><<<((NPAD - NNODES) * 128 / 8 + TB - 1) / TB, TB>>>();

    // Layer 2: I=128, N2=128
    conv_w_kernel<128, 64><<<(2 * 64 * 128 / 8 + TB - 1) / TB, TB>>>(Wl2, Wr2);
    mma_gemm_kernel<128, 128><<<dim3(MT, 2), 256>>>();
    gather_add_kernel<64, 1><<<GW, TB>>>(b2, nullptr);    // -> g_xh/g_xl [n][64]
    zero_pad_kernel<64><<<((NPAD - NNODES) * 64 / 8 + TB - 1) / TB, TB>>>();

    // Layer 3: I=64, N2=256
    conv_w_kernel<64, 128><<<(2 * 128 * 64 / 8 + TB - 1) / TB, TB>>>(Wl3, Wr3);
    mma_gemm_kernel<64, 256><<<dim3(MT, 4), 256>>>();
    gather_add_kernel<128, 0><<<GW, TB>>>(b3, out);       // -> d_out f32
}

// round 14
// speedup vs baseline: 1.5033x; 1.0524x over previous
#include <cuda_runtime.h>
#include <cuda_fp16.h>
#include <cstdint>

#define NNODES 50000
#define NPAD   50048           // 391 * 128
#define NEDGES 800000
#define SCAN_T 1024

// ======================= device-global scratch =======================
__device__ __align__(16) int   g_deg[NNODES];
__device__ __align__(16) int   g_rowptr[NNODES + 1];
__device__ __align__(16) int   g_cursor[NNODES];
__device__ __align__(16) int   g_csr_src[NEDGES];
__device__ __align__(16) float g_inv[NNODES];
__device__ __align__(16) float g_z[NNODES * 256];    // [z_l | z_r] stacked
__device__ __align__(16) float g_hf[NNODES * 64];    // f32 h2 (layer-3 gather src)
// fp16 hi/lo splits (ushort); A layout stays [NPAD x 128] for ALL layers
__device__ __align__(16) unsigned short g_xh[NPAD * 128];
__device__ __align__(16) unsigned short g_xl[NPAD * 128];
__device__ __align__(16) unsigned short g_wh[256 * 128];
__device__ __align__(16) unsigned short g_wl[256 * 128];

// ======================= CSR build =======================
__global__ void zero_deg_kernel() {
    int i = blockIdx.x * blockDim.x + threadIdx.x;
    if (i < NNODES) g_deg[i] = 0;
}
__global__ void count_kernel(const int* __restrict__ ei) {
    int e = blockIdx.x * blockDim.x + threadIdx.x;
    if (e < NEDGES) atomicAdd(&g_deg[ei[NEDGES + e]], 1);
}
__global__ void scan_kernel() {
    __shared__ int partial[SCAN_T];
    const int t = threadIdx.x;
    const int CH = (NNODES + SCAN_T - 1) / SCAN_T;
    const int base = t * CH;
    int s = 0;
    for (int i = 0; i < CH; i++) {
        int idx = base + i;
        if (idx < NNODES) s += g_deg[idx];
    }
    partial[t] = s;
    __syncthreads();
    for (int off = 1; off < SCAN_T; off <<= 1) {
        int add = (t >= off) ? partial[t - off] : 0;
        __syncthreads();
        partial[t] += add;
        __syncthreads();
    }
    int run = (t == 0) ? 0 : partial[t - 1];
    for (int i = 0; i < CH; i++) {
        int idx = base + i;
        if (idx < NNODES) {
            g_rowptr[idx] = run;
            g_cursor[idx] = run;
            g_inv[idx] = 1.0f / fmaxf((float)g_deg[idx], 1.0f);
            run += g_deg[idx];
        }
    }
    if (t == SCAN_T - 1) g_rowptr[NNODES] = partial[SCAN_T - 1];
}
__global__ void fill_kernel(const int* __restrict__ ei) {
    int e = blockIdx.x * blockDim.x + threadIdx.x;
    if (e < NEDGES) {
        int dst = ei[NEDGES + e];
        int slot = atomicAdd(&g_cursor[dst], 1);
        g_csr_src[slot] = ei[e];
    }
}

// ======================= fp16 split helpers =======================
union U4H8 { uint4 v; unsigned short u16[8]; };

__device__ __forceinline__ void split_f16(float f, unsigned short& hi, unsigned short& lo) {
    __half h = __float2half_rn(f);
    hi = __half_as_ushort(h);
    __half l = __float2half_rn(f - __half2float(h));
    lo = __half_as_ushort(l);
}

// input x -> g_xh/g_xl [NPAD x 128], pad rows zeroed (stay zero all run).
__global__ void conv_x_kernel(const float* __restrict__ x) {
    int t = blockIdx.x * blockDim.x + threadIdx.x;
    if (t >= NPAD * 128 / 8) return;
    int base = t * 8;
    int row = base / 128;
    U4H8 hi, lo;
    hi.v = make_uint4(0, 0, 0, 0);
    lo.v = make_uint4(0, 0, 0, 0);
    if (row < NNODES) {
        const float4* src = reinterpret_cast<const float4*>(x + base);
        float4 f0 = src[0], f1 = src[1];
        float f[8] = {f0.x, f0.y, f0.z, f0.w, f1.x, f1.y, f1.z, f1.w};
#pragma unroll
        for (int i = 0; i < 8; i++) split_f16(f[i], hi.u16[i], lo.u16[i]);
    }
    reinterpret_cast<uint4*>(g_xh)[t] = hi.v;
    reinterpret_cast<uint4*>(g_xl)[t] = lo.v;
}

// W = [Wl;Wr] stacked (2O rows x I) -> g_wh/g_wl
template <int I, int O>
__global__ void conv_w_kernel(const float* __restrict__ Wl,
                              const float* __restrict__ Wr) {
    int t = blockIdx.x * blockDim.x + threadIdx.x;
    if (t >= 2 * O * I / 8) return;
    int base = t * 8;
    int j = base / I;
    int k = base % I;
    const float* wrow = (j < O) ? (Wl + (size_t)j * I) : (Wr + (size_t)(j - O) * I);
    const float4* src = reinterpret_cast<const float4*>(wrow + k);
    float4 f0 = src[0], f1 = src[1];
    float f[8] = {f0.x, f0.y, f0.z, f0.w, f1.x, f1.y, f1.z, f1.w};
    U4H8 hi, lo;
#pragma unroll
    for (int i = 0; i < 8; i++) split_f16(f[i], hi.u16[i], lo.u16[i]);
    reinterpret_cast<uint4*>(g_wh)[t] = hi.v;
    reinterpret_cast<uint4*>(g_wl)[t] = lo.v;
}

// W_cat = [Wl | Wr] side-by-side (O rows x 2*IH cols) -> g_wh/g_wl
template <int IH, int O>   // IH = half width (per-matrix input dim)
__global__ void conv_wcat_kernel(const float* __restrict__ Wl,
                                 const float* __restrict__ Wr) {
    constexpr int I = 2 * IH;
    int t = blockIdx.x * blockDim.x + threadIdx.x;
    if (t >= O * I / 8) return;
    int base = t * 8;
    int j = base / I;
    int k = base % I;   // 8-chunk lies entirely in one half (8 | IH)
    const float* src = (k < IH) ? (Wl + (size_t)j * IH + k)
                                : (Wr + (size_t)j * IH + (k - IH));
    const float4* s4 = reinterpret_cast<const float4*>(src);
    float4 f0 = s4[0], f1 = s4[1];
    float f[8] = {f0.x, f0.y, f0.z, f0.w, f1.x, f1.y, f1.z, f1.w};
    U4H8 hi, lo;
#pragma unroll
    for (int i = 0; i < 8; i++) split_f16(f[i], hi.u16[i], lo.u16[i]);
    reinterpret_cast<uint4*>(g_wh)[t] = hi.v;
    reinterpret_cast<uint4*>(g_wl)[t] = lo.v;
}

// ======================= split-fp16 mma.sync GEMM =======================
// z = A @ W^T via D = Ah*Bh + Ah*Bl + Al*Bh (fp32 acc), m16n8k16.
// Block: 256 thr (8 warps), BM=128 x BN=64, K-chunk=16. A layout [NPAD x I].
// OMODE 0: write g_z stacked rows of width N2 (no bias).
// OMODE 1: write outp rows of width N2 with bias added.
template <int I, int N2, int OMODE>
__global__ __launch_bounds__(256)
void mma_gemm_kernel(const float* __restrict__ bias, float* __restrict__ outp) {
    __shared__ __align__(16) unsigned int ash[128][12];
    __shared__ __align__(16) unsigned int asl[128][12];
    __shared__ __align__(16) unsigned int bsh[64][12];
    __shared__ __align__(16) unsigned int bsl[64][12];

    const int t    = threadIdx.x;
    const int w    = t >> 5;
    const int lane = t & 31;
    const int gid  = lane >> 2;
    const int tig  = lane & 3;
    const int m0   = blockIdx.x * 128;
    const int n0   = blockIdx.y * 64;
    const int wrow = w * 16;

    float acc[8][4];
#pragma unroll
    for (int j = 0; j < 8; j++)
#pragma unroll
        for (int c = 0; c < 4; c++) acc[j][c] = 0.0f;

    const int arow = t >> 1, aq = t & 1;
    const int tb = t & 127;
    const int brow = tb >> 1, bq = tb & 1;

    for (int k0 = 0; k0 < I; k0 += 16) {
        {
            uint4 vh = *reinterpret_cast<const uint4*>(
                g_xh + (size_t)(m0 + arow) * I + k0 + 8 * aq);
            uint4 vl = *reinterpret_cast<const uint4*>(
                g_xl + (size_t)(m0 + arow) * I + k0 + 8 * aq);
            *reinterpret_cast<uint4*>(&ash[arow][4 * aq]) = vh;
            *reinterpret_cast<uint4*>(&asl[arow][4 * aq]) = vl;
            const unsigned short* W = (t < 128) ? g_wh : g_wl;
            uint4 vb = *reinterpret_cast<const uint4*>(
                W + (size_t)(n0 + brow) * I + k0 + 8 * bq);
            if (t < 128)
                *reinterpret_cast<uint4*>(&bsh[brow][4 * bq]) = vb;
            else
                *reinterpret_cast<uint4*>(&bsl[brow][4 * bq]) = vb;
        }
        __syncthreads();
        {
            unsigned int ah0 = ash[wrow + gid][tig];
            unsigned int ah1 = ash[wrow + gid + 8][tig];
            unsigned int ah2 = ash[wrow + gid][tig + 4];
            unsigned int ah3 = ash[wrow + gid + 8][tig + 4];
            unsigned int al0 = asl[wrow + gid][tig];
            unsigned int al1 = asl[wrow + gid + 8][tig];
            unsigned int al2 = asl[wrow + gid][tig + 4];
            unsigned int al3 = asl[wrow + gid + 8][tig + 4];
#pragma unroll
            for (int j = 0; j < 8; j++) {
                unsigned int bh0 = bsh[8 * j + gid][tig];
                unsigned int bh1 = bsh[8 * j + gid][tig + 4];
                unsigned int bl0 = bsl[8 * j + gid][tig];
                unsigned int bl1 = bsl[8 * j + gid][tig + 4];
                asm volatile(
                    "mma.sync.aligned.m16n8k16.row.col.f32.f16.f16.f32 "
                    "{%0,%1,%2,%3}, {%4,%5,%6,%7}, {%8,%9}, {%0,%1,%2,%3};"
                    : "+f"(acc[j][0]), "+f"(acc[j][1]),
                      "+f"(acc[j][2]), "+f"(acc[j][3])
                    : "r"(ah0), "r"(ah1), "r"(ah2), "r"(ah3), "r"(bh0), "r"(bh1));
                asm volatile(
                    "mma.sync.aligned.m16n8k16.row.col.f32.f16.f16.f32 "
                    "{%0,%1,%2,%3}, {%4,%5,%6,%7}, {%8,%9}, {%0,%1,%2,%3};"
                    : "+f"(acc[j][0]), "+f"(acc[j][1]),
                      "+f"(acc[j][2]), "+f"(acc[j][3])
                    : "r"(ah0), "r"(ah1), "r"(ah2), "r"(ah3), "r"(bl0), "r"(bl1));
                asm volatile(
                    "mma.sync.aligned.m16n8k16.row.col.f32.f16.f16.f32 "
                    "{%0,%1,%2,%3}, {%4,%5,%6,%7}, {%8,%9}, {%0,%1,%2,%3};"
                    : "+f"(acc[j][0]), "+f"(acc[j][1]),
                      "+f"(acc[j][2]), "+f"(acc[j][3])
                    : "r"(al0), "r"(al1), "r"(al2), "r"(al3), "r"(bh0), "r"(bh1));
            }
        }
        __syncthreads();
    }

    const int node0 = m0 + wrow + gid;
    const int node1 = node0 + 8;
#pragma unroll
    for (int j = 0; j < 8; j++) {
        int col = n0 + 8 * j + 2 * tig;
        float bx = 0.f, by = 0.f;
        if (OMODE == 1) { bx = bias[col]; by = bias[col + 1]; }
        float* dst = (OMODE == 0) ? g_z : outp;
        if (node0 < NNODES)
            *reinterpret_cast<float2*>(dst + (size_t)node0 * N2 + col) =
                make_float2(acc[j][0] + bx, acc[j][1] + by);
        if (node1 < NNODES)
            *reinterpret_cast<float2*>(dst + (size_t)node1 * N2 + col) =
                make_float2(acc[j][2] + bx, acc[j][3] + by);
    }
}

// ======================= gather-add =======================
// h[n] = inv[n]*sum z_l[src] + z_r[n] + b.
// MODE 0 (O=128): f32 -> outp.
// MODE 1 (O=128): fp16 split -> g_xh/g_xl [n][128].
// MODE 2 (O=64):  fp16 split -> RIGHT half of g_xh/g_xl [n][128], f32 -> g_hf.
template <int O, int MODE>
__global__ void gather_add_kernel(const float* __restrict__ b,
                                  float* __restrict__ outp) {
    int warp = (blockIdx.x * blockDim.x + threadIdx.x) >> 5;
    int lane = threadIdx.x & 31;
    if (warp >= NNODES) return;
    int beg = g_rowptr[warp];
    int end = g_rowptr[warp + 1];
    float inv = g_inv[warp];
    constexpr int RS = 2 * O;

    if (O == 128) {
        float4 acc = make_float4(0.f, 0.f, 0.f, 0.f);
        int j = beg;
        for (; j + 3 < end; j += 4) {
            int s0 = g_csr_src[j], s1 = g_csr_src[j + 1];
            int s2 = g_csr_src[j + 2], s3 = g_csr_src[j + 3];
            float4 v0 = reinterpret_cast<const float4*>(g_z + (size_t)s0 * RS)[lane];
            float4 v1 = reinterpret_cast<const float4*>(g_z + (size_t)s1 * RS)[lane];
            float4 v2 = reinterpret_cast<const float4*>(g_z + (size_t)s2 * RS)[lane];
            float4 v3 = reinterpret_cast<const float4*>(g_z + (size_t)s3 * RS)[lane];
            acc.x += (v0.x + v1.x) + (v2.x + v3.x);
            acc.y += (v0.y + v1.y) + (v2.y + v3.y);
            acc.z += (v0.z + v1.z) + (v2.z + v3.z);
            acc.w += (v0.w + v1.w) + (v2.w + v3.w);
        }
        for (; j < end; j++) {
            int s0 = g_csr_src[j];
            float4 v0 = reinterpret_cast<const float4*>(g_z + (size_t)s0 * RS)[lane];
            acc.x += v0.x; acc.y += v0.y; acc.z += v0.z; acc.w += v0.w;
        }
        float4 zr = reinterpret_cast<const float4*>(g_z + (size_t)warp * RS + O)[lane];
        float4 bb = reinterpret_cast<const float4*>(b)[lane];
        float4 res;
        res.x = acc.x * inv + zr.x + bb.x;
        res.y = acc.y * inv + zr.y + bb.y;
        res.z = acc.z * inv + zr.z + bb.z;
        res.w = acc.w * inv + zr.w + bb.w;
        if (MODE == 0) {
            reinterpret_cast<float4*>(outp + (size_t)warp * O)[lane] = res;
        } else {
            unsigned short h[4], l[4];
            split_f16(res.x, h[0], l[0]);
            split_f16(res.y, h[1], l[1]);
            split_f16(res.z, h[2], l[2]);
            split_f16(res.w, h[3], l[3]);
            reinterpret_cast<uint2*>(g_xh + (size_t)warp * 128)[lane] =
                *reinterpret_cast<uint2*>(h);
            reinterpret_cast<uint2*>(g_xl + (size_t)warp * 128)[lane] =
                *reinterpret_cast<uint2*>(l);
        }
    } else {
        float2 acc = make_float2(0.f, 0.f);
        int j = beg;
        for (; j + 3 < end; j += 4) {
            int s0 = g_csr_src[j], s1 = g_csr_src[j + 1];
            int s2 = g_csr_src[j + 2], s3 = g_csr_src[j + 3];
            float2 v0 = reinterpret_cast<const float2*>(g_z + (size_t)s0 * RS)[lane];
            float2 v1 = reinterpret_cast<const float2*>(g_z + (size_t)s1 * RS)[lane];
            float2 v2 = reinterpret_cast<const float2*>(g_z + (size_t)s2 * RS)[lane];
            float2 v3 = reinterpret_cast<const float2*>(g_z + (size_t)s3 * RS)[lane];
            acc.x += (v0.x + v1.x) + (v2.x + v3.x);
            acc.y += (v0.y + v1.y) + (v2.y + v3.y);
        }
        for (; j < end; j++) {
            int s0 = g_csr_src[j];
            float2 v0 = reinterpret_cast<const float2*>(g_z + (size_t)s0 * RS)[lane];
            acc.x += v0.x; acc.y += v0.y;
        }
        float2 zr = reinterpret_cast<const float2*>(g_z + (size_t)warp * RS + O)[lane];
        float2 bb = reinterpret_cast<const float2*>(b)[lane];
        float2 res;
        res.x = acc.x * inv + zr.x + bb.x;
        res.y = acc.y * inv + zr.y + bb.y;
        // MODE 2: fp16 split -> right half of A buffer; f32 -> g_hf
        unsigned short h[2], l[2];
        split_f16(res.x, h[0], l[0]);
        split_f16(res.y, h[1], l[1]);
        reinterpret_cast<unsigned int*>(g_xh + (size_t)warp * 128 + 64)[lane] =
            *reinterpret_cast<unsigned int*>(h);
        reinterpret_cast<unsigned int*>(g_xl + (size_t)warp * 128 + 64)[lane] =
            *reinterpret_cast<unsigned int*>(l);
        reinterpret_cast<float2*>(g_hf + (size_t)warp * 64)[lane] = res;
    }
}

// gather-mean over g_hf (64-wide) -> fp16 split into LEFT half of A buffer.
__global__ void gather_mean_split_kernel() {
    int warp = (blockIdx.x * blockDim.x + threadIdx.x) >> 5;
    int lane = threadIdx.x & 31;
    if (warp >= NNODES) return;
    int beg = g_rowptr[warp];
    int end = g_rowptr[warp + 1];
    float inv = g_inv[warp];

    float2 acc = make_float2(0.f, 0.f);
    int j = beg;
    for (; j + 3 < end; j += 4) {
        int s0 = g_csr_src[j], s1 = g_csr_src[j + 1];
        int s2 = g_csr_src[j + 2], s3 = g_csr_src[j + 3];
        float2 v0 = reinterpret_cast<const float2*>(g_hf + (size_t)s0 * 64)[lane];
        float2 v1 = reinterpret_cast<const float2*>(g_hf + (size_t)s1 * 64)[lane];
        float2 v2 = reinterpret_cast<const float2*>(g_hf + (size_t)s2 * 64)[lane];
        float2 v3 = reinterpret_cast<const float2*>(g_hf + (size_t)s3 * 64)[lane];
        acc.x += (v0.x + v1.x) + (v2.x + v3.x);
        acc.y += (v0.y + v1.y) + (v2.y + v3.y);
    }
    for (; j < end; j++) {
        int s0 = g_csr_src[j];
        float2 v0 = reinterpret_cast<const float2*>(g_hf + (size_t)s0 * 64)[lane];
        acc.x += v0.x; acc.y += v0.y;
    }
    acc.x *= inv; acc.y *= inv;
    unsigned short h[2], l[2];
    split_f16(acc.x, h[0], l[0]);
    split_f16(acc.y, h[1], l[1]);
    reinterpret_cast<unsigned int*>(g_xh + (size_t)warp * 128)[lane] =
        *reinterpret_cast<unsigned int*>(h);
    reinterpret_cast<unsigned int*>(g_xl + (size_t)warp * 128)[lane] =
        *reinterpret_cast<unsigned int*>(l);
}

// ======================= launch =======================
extern "C" void kernel_launch(void* const* d_in, const int* in_sizes, int n_in,
                              void* d_out, int out_size) {
    const float* x   = (const float*)d_in[0];
    const int*   ei  = (const int*)d_in[1];   // int32 (JAX x64 disabled)
    const float* Wl1 = (const float*)d_in[2];
    const float* b1  = (const float*)d_in[3];
    const float* Wr1 = (const float*)d_in[4];
    const float* Wl2 = (const float*)d_in[5];
    const float* b2  = (const float*)d_in[6];
    const float* Wr2 = (const float*)d_in[7];
    const float* Wl3 = (const float*)d_in[8];
    const float* b3  = (const float*)d_in[9];
    const float* Wr3 = (const float*)d_in[10];
    float* out = (float*)d_out;

    const int TB = 256;
    const int MT = NPAD / 128;                    // 391 M-tiles
    const int GW = (NNODES * 32 + TB - 1) / TB;   // gather: warp/node

    // CSR build
    zero_deg_kernel<<<(NNODES + TB - 1) / TB, TB>>>();
    count_kernel<<<(NEDGES + TB - 1) / TB, TB>>>(ei);
    scan_kernel<<<1, SCAN_T>>>();
    fill_kernel<<<(NEDGES + TB - 1) / TB, TB>>>(ei);

    // Layer 1: I=128, N2=256
    conv_x_kernel<<<(NPAD * 128 / 8 + TB - 1) / TB, TB>>>(x);
    conv_w_kernel<128, 128><<<(2 * 128 * 128 / 8 + TB - 1) / TB, TB>>>(Wl1, Wr1);
    mma_gemm_kernel<128, 256, 0><<<dim3(MT, 4), 256>>>(nullptr, nullptr);
    gather_add_kernel<128, 1><<<GW, TB>>>(b1, nullptr);   // h1 -> A[n][0..128)

    // Layer 2: I=128, N2=128
    conv_w_kernel<128, 64><<<(2 * 64 * 128 / 8 + TB - 1) / TB, TB>>>(Wl2, Wr2);
    mma_gemm_kernel<128, 128, 0><<<dim3(MT, 2), 256>>>(nullptr, nullptr);
    gather_add_kernel<64, 2><<<GW, TB>>>(b2, nullptr);    // h2 -> A[n][64..128) + g_hf

    // Layer 3: A = [mean(h2) | h2], W_cat = [Wl3 | Wr3]; GEMM writes d_out + b3
    gather_mean_split_kernel<<<GW, TB>>>();               // mean -> A[n][0..64)
    conv_wcat_kernel<64, 128><<<(128 * 128 / 8 + TB - 1) / TB, TB>>>(Wl3, Wr3);
    mma_gemm_kernel<128, 128, 1><<<dim3(MT, 2), 256>>>(b3, out);
}

// round 15
// speedup vs baseline: 1.8233x; 1.2128x over previous
#include <cuda_runtime.h>
#include <cuda_fp16.h>
#include <cstdint>

#define NNODES 50000
#define NPAD   50048           // 391 * 128
#define NEDGES 800000
#define SCAN_T 1024

// ======================= device-global scratch =======================
__device__ __align__(16) int   g_deg[NNODES];
__device__ __align__(16) int   g_rowptr[NNODES + 1];
__device__ __align__(16) int   g_cursor[NNODES];
__device__ __align__(16) int   g_csr_src[NEDGES];
__device__ __align__(16) float g_inv[NNODES];
__device__ __align__(16) float g_z[NNODES * 256];    // [z_l | z_r] stacked
__device__ __align__(16) float g_hf[NNODES * 64];    // f32 h2 (layer-3 gather src)
// fp16 hi/lo splits; A layout stays [NPAD x 128] for ALL layers
__device__ __align__(16) unsigned short g_xh[NPAD * 128];
__device__ __align__(16) unsigned short g_xl[NPAD * 128];
// per-layer weight buffers (so all conversions can run early on the side stream)
__device__ __align__(16) unsigned short g_w1h[256 * 128];
__device__ __align__(16) unsigned short g_w1l[256 * 128];
__device__ __align__(16) unsigned short g_w2h[128 * 128];
__device__ __align__(16) unsigned short g_w2l[128 * 128];
__device__ __align__(16) unsigned short g_w3h[128 * 128];
__device__ __align__(16) unsigned short g_w3l[128 * 128];

template <int WSEL>
__device__ __forceinline__ const unsigned short* wsel_h() {
    if (WSEL == 1) return g_w1h;
    if (WSEL == 2) return g_w2h;
    return g_w3h;
}
template <int WSEL>
__device__ __forceinline__ const unsigned short* wsel_l() {
    if (WSEL == 1) return g_w1l;
    if (WSEL == 2) return g_w2l;
    return g_w3l;
}
template <int WSEL>
__device__ __forceinline__ unsigned short* wsel_h_mut() {
    if (WSEL == 1) return g_w1h;
    if (WSEL == 2) return g_w2h;
    return g_w3h;
}
template <int WSEL>
__device__ __forceinline__ unsigned short* wsel_l_mut() {
    if (WSEL == 1) return g_w1l;
    if (WSEL == 2) return g_w2l;
    return g_w3l;
}

// ======================= CSR build =======================
__global__ void zero_deg_kernel() {
    int i = blockIdx.x * blockDim.x + threadIdx.x;
    if (i < NNODES) g_deg[i] = 0;
}
__global__ void count_kernel(const int* __restrict__ ei) {
    int e = blockIdx.x * blockDim.x + threadIdx.x;
    if (e < NEDGES) atomicAdd(&g_deg[ei[NEDGES + e]], 1);
}
__global__ void scan_kernel() {
    __shared__ int partial[SCAN_T];
    const int t = threadIdx.x;
    const int CH = (NNODES + SCAN_T - 1) / SCAN_T;
    const int base = t * CH;
    int s = 0;
    for (int i = 0; i < CH; i++) {
        int idx = base + i;
        if (idx < NNODES) s += g_deg[idx];
    }
    partial[t] = s;
    __syncthreads();
    for (int off = 1; off < SCAN_T; off <<= 1) {
        int add = (t >= off) ? partial[t - off] : 0;
        __syncthreads();
        partial[t] += add;
        __syncthreads();
    }
    int run = (t == 0) ? 0 : partial[t - 1];
    for (int i = 0; i < CH; i++) {
        int idx = base + i;
        if (idx < NNODES) {
            g_rowptr[idx] = run;
            g_cursor[idx] = run;
            g_inv[idx] = 1.0f / fmaxf((float)g_deg[idx], 1.0f);
            run += g_deg[idx];
        }
    }
    if (t == SCAN_T - 1) g_rowptr[NNODES] = partial[SCAN_T - 1];
}
__global__ void fill_kernel(const int* __restrict__ ei) {
    int e = blockIdx.x * blockDim.x + threadIdx.x;
    if (e < NEDGES) {
        int dst = ei[NEDGES + e];
        int slot = atomicAdd(&g_cursor[dst], 1);
        g_csr_src[slot] = ei[e];
    }
}

// ======================= fp16 split helpers =======================
union U4H8 { uint4 v; unsigned short u16[8]; };

__device__ __forceinline__ void split_f16(float f, unsigned short& hi, unsigned short& lo) {
    __half h = __float2half_rn(f);
    hi = __half_as_ushort(h);
    __half l = __float2half_rn(f - __half2float(h));
    lo = __half_as_ushort(l);
}

// input x -> g_xh/g_xl [NPAD x 128], pad rows zeroed (stay zero all run).
__global__ void conv_x_kernel(const float* __restrict__ x) {
    int t = blockIdx.x * blockDim.x + threadIdx.x;
    if (t >= NPAD * 128 / 8) return;
    int base = t * 8;
    int row = base / 128;
    U4H8 hi, lo;
    hi.v = make_uint4(0, 0, 0, 0);
    lo.v = make_uint4(0, 0, 0, 0);
    if (row < NNODES) {
        const float4* src = reinterpret_cast<const float4*>(x + base);
        float4 f0 = src[0], f1 = src[1];
        float f[8] = {f0.x, f0.y, f0.z, f0.w, f1.x, f1.y, f1.z, f1.w};
#pragma unroll
        for (int i = 0; i < 8; i++) split_f16(f[i], hi.u16[i], lo.u16[i]);
    }
    reinterpret_cast<uint4*>(g_xh)[t] = hi.v;
    reinterpret_cast<uint4*>(g_xl)[t] = lo.v;
}

// W = [Wl;Wr] stacked (2O rows x I) -> weight buffer WSEL
template <int I, int O, int WSEL>
__global__ void conv_w_kernel(const float* __restrict__ Wl,
                              const float* __restrict__ Wr) {
    int t = blockIdx.x * blockDim.x + threadIdx.x;
    if (t >= 2 * O * I / 8) return;
    int base = t * 8;
    int j = base / I;
    int k = base % I;
    const float* wrow = (j < O) ? (Wl + (size_t)j * I) : (Wr + (size_t)(j - O) * I);
    const float4* src = reinterpret_cast<const float4*>(wrow + k);
    float4 f0 = src[0], f1 = src[1];
    float f[8] = {f0.x, f0.y, f0.z, f0.w, f1.x, f1.y, f1.z, f1.w};
    U4H8 hi, lo;
#pragma unroll
    for (int i = 0; i < 8; i++) split_f16(f[i], hi.u16[i], lo.u16[i]);
    reinterpret_cast<uint4*>(wsel_h_mut<WSEL>())[t] = hi.v;
    reinterpret_cast<uint4*>(wsel_l_mut<WSEL>())[t] = lo.v;
}

// W_cat = [Wl | Wr] side-by-side (O rows x 2*IH cols) -> weight buffer WSEL
template <int IH, int O, int WSEL>
__global__ void conv_wcat_kernel(const float* __restrict__ Wl,
                                 const float* __restrict__ Wr) {
    constexpr int I = 2 * IH;
    int t = blockIdx.x * blockDim.x + threadIdx.x;
    if (t >= O * I / 8) return;
    int base = t * 8;
    int j = base / I;
    int k = base % I;
    const float* src = (k < IH) ? (Wl + (size_t)j * IH + k)
                                : (Wr + (size_t)j * IH + (k - IH));
    const float4* s4 = reinterpret_cast<const float4*>(src);
    float4 f0 = s4[0], f1 = s4[1];
    float f[8] = {f0.x, f0.y, f0.z, f0.w, f1.x, f1.y, f1.z, f1.w};
    U4H8 hi, lo;
#pragma unroll
    for (int i = 0; i < 8; i++) split_f16(f[i], hi.u16[i], lo.u16[i]);
    reinterpret_cast<uint4*>(wsel_h_mut<WSEL>())[t] = hi.v;
    reinterpret_cast<uint4*>(wsel_l_mut<WSEL>())[t] = lo.v;
}

// ======================= split-fp16 mma.sync GEMM =======================
// z = A @ W^T via D = Ah*Bh + Ah*Bl + Al*Bh (fp32 acc), m16n8k16.
// OMODE 0: write g_z (no bias). OMODE 1: write outp with bias.
template <int I, int N2, int OMODE, int WSEL>
__global__ __launch_bounds__(256)
void mma_gemm_kernel(const float* __restrict__ bias, float* __restrict__ outp) {
    __shared__ __align__(16) unsigned int ash[128][12];
    __shared__ __align__(16) unsigned int asl[128][12];
    __shared__ __align__(16) unsigned int bsh[64][12];
    __shared__ __align__(16) unsigned int bsl[64][12];

    const int t    = threadIdx.x;
    const int w    = t >> 5;
    const int lane = t & 31;
    const int gid  = lane >> 2;
    const int tig  = lane & 3;
    const int m0   = blockIdx.x * 128;
    const int n0   = blockIdx.y * 64;
    const int wrow = w * 16;

    float acc[8][4];
#pragma unroll
    for (int j = 0; j < 8; j++)
#pragma unroll
        for (int c = 0; c < 4; c++) acc[j][c] = 0.0f;

    const int arow = t >> 1, aq = t & 1;
    const int tb = t & 127;
    const int brow = tb >> 1, bq = tb & 1;

    for (int k0 = 0; k0 < I; k0 += 16) {
        {
            uint4 vh = *reinterpret_cast<const uint4*>(
                g_xh + (size_t)(m0 + arow) * I + k0 + 8 * aq);
            uint4 vl = *reinterpret_cast<const uint4*>(
                g_xl + (size_t)(m0 + arow) * I + k0 + 8 * aq);
            *reinterpret_cast<uint4*>(&ash[arow][4 * aq]) = vh;
            *reinterpret_cast<uint4*>(&asl[arow][4 * aq]) = vl;
            const unsigned short* W = (t < 128) ? wsel_h<WSEL>() : wsel_l<WSEL>();
            uint4 vb = *reinterpret_cast<const uint4*>(
                W + (size_t)(n0 + brow) * I + k0 + 8 * bq);
            if (t < 128)
                *reinterpret_cast<uint4*>(&bsh[brow][4 * bq]) = vb;
            else
                *reinterpret_cast<uint4*>(&bsl[brow][4 * bq]) = vb;
        }
        __syncthreads();
        {
            unsigned int ah0 = ash[wrow + gid][tig];
            unsigned int ah1 = ash[wrow + gid + 8][tig];
            unsigned int ah2 = ash[wrow + gid][tig + 4];
            unsigned int ah3 = ash[wrow + gid + 8][tig + 4];
            unsigned int al0 = asl[wrow + gid][tig];
            unsigned int al1 = asl[wrow + gid + 8][tig];
            unsigned int al2 = asl[wrow + gid][tig + 4];
            unsigned int al3 = asl[wrow + gid + 8][tig + 4];
#pragma unroll
            for (int j = 0; j < 8; j++) {
                unsigned int bh0 = bsh[8 * j + gid][tig];
                unsigned int bh1 = bsh[8 * j + gid][tig + 4];
                unsigned int bl0 = bsl[8 * j + gid][tig];
                unsigned int bl1 = bsl[8 * j + gid][tig + 4];
                asm volatile(
                    "mma.sync.aligned.m16n8k16.row.col.f32.f16.f16.f32 "
                    "{%0,%1,%2,%3}, {%4,%5,%6,%7}, {%8,%9}, {%0,%1,%2,%3};"
                    : "+f"(acc[j][0]), "+f"(acc[j][1]),
                      "+f"(acc[j][2]), "+f"(acc[j][3])
                    : "r"(ah0), "r"(ah1), "r"(ah2), "r"(ah3), "r"(bh0), "r"(bh1));
                asm volatile(
                    "mma.sync.aligned.m16n8k16.row.col.f32.f16.f16.f32 "
                    "{%0,%1,%2,%3}, {%4,%5,%6,%7}, {%8,%9}, {%0,%1,%2,%3};"
                    : "+f"(acc[j][0]), "+f"(acc[j][1]),
                      "+f"(acc[j][2]), "+f"(acc[j][3])
                    : "r"(ah0), "r"(ah1), "r"(ah2), "r"(ah3), "r"(bl0), "r"(bl1));
                asm volatile(
                    "mma.sync.aligned.m16n8k16.row.col.f32.f16.f16.f32 "
                    "{%0,%1,%2,%3}, {%4,%5,%6,%7}, {%8,%9}, {%0,%1,%2,%3};"
                    : "+f"(acc[j][0]), "+f"(acc[j][1]),
                      "+f"(acc[j][2]), "+f"(acc[j][3])
                    : "r"(al0), "r"(al1), "r"(al2), "r"(al3), "r"(bh0), "r"(bh1));
            }
        }
        __syncthreads();
    }

    const int node0 = m0 + wrow + gid;
    const int node1 = node0 + 8;
#pragma unroll
    for (int j = 0; j < 8; j++) {
        int col = n0 + 8 * j + 2 * tig;
        float bx = 0.f, by = 0.f;
        if (OMODE == 1) { bx = bias[col]; by = bias[col + 1]; }
        float* dst = (OMODE == 0) ? g_z : outp;
        if (node0 < NNODES)
            *reinterpret_cast<float2*>(dst + (size_t)node0 * N2 + col) =
                make_float2(acc[j][0] + bx, acc[j][1] + by);
        if (node1 < NNODES)
            *reinterpret_cast<float2*>(dst + (size_t)node1 * N2 + col) =
                make_float2(acc[j][2] + bx, acc[j][3] + by);
    }
}

// ======================= gather-add =======================
// MODE 0 (O=128): f32 -> outp.
// MODE 1 (O=128): fp16 split -> g_xh/g_xl [n][128].
// MODE 2 (O=64):  fp16 split -> RIGHT half of g_xh/g_xl [n][128], f32 -> g_hf.
template <int O, int MODE>
__global__ void gather_add_kernel(const float* __restrict__ b,
                                  float* __restrict__ outp) {
    int warp = (blockIdx.x * blockDim.x + threadIdx.x) >> 5;
    int lane = threadIdx.x & 31;
    if (warp >= NNODES) return;
    int beg = g_rowptr[warp];
    int end = g_rowptr[warp + 1];
    float inv = g_inv[warp];
    constexpr int RS = 2 * O;

    if (O == 128) {
        float4 acc = make_float4(0.f, 0.f, 0.f, 0.f);
        int j = beg;
        for (; j + 3 < end; j += 4) {
            int s0 = g_csr_src[j], s1 = g_csr_src[j + 1];
            int s2 = g_csr_src[j + 2], s3 = g_csr_src[j + 3];
            float4 v0 = reinterpret_cast<const float4*>(g_z + (size_t)s0 * RS)[lane];
            float4 v1 = reinterpret_cast<const float4*>(g_z + (size_t)s1 * RS)[lane];
            float4 v2 = reinterpret_cast<const float4*>(g_z + (size_t)s2 * RS)[lane];
            float4 v3 = reinterpret_cast<const float4*>(g_z + (size_t)s3 * RS)[lane];
            acc.x += (v0.x + v1.x) + (v2.x + v3.x);
            acc.y += (v0.y + v1.y) + (v2.y + v3.y);
            acc.z += (v0.z + v1.z) + (v2.z + v3.z);
            acc.w += (v0.w + v1.w) + (v2.w + v3.w);
        }
        for (; j < end; j++) {
            int s0 = g_csr_src[j];
            float4 v0 = reinterpret_cast<const float4*>(g_z + (size_t)s0 * RS)[lane];
            acc.x += v0.x; acc.y += v0.y; acc.z += v0.z; acc.w += v0.w;
        }
        float4 zr = reinterpret_cast<const float4*>(g_z + (size_t)warp * RS + O)[lane];
        float4 bb = reinterpret_cast<const float4*>(b)[lane];
        float4 res;
        res.x = acc.x * inv + zr.x + bb.x;
        res.y = acc.y * inv + zr.y + bb.y;
        res.z = acc.z * inv + zr.z + bb.z;
        res.w = acc.w * inv + zr.w + bb.w;
        if (MODE == 0) {
            reinterpret_cast<float4*>(outp + (size_t)warp * O)[lane] = res;
        } else {
            unsigned short h[4], l[4];
            split_f16(res.x, h[0], l[0]);
            split_f16(res.y, h[1], l[1]);
            split_f16(res.z, h[2], l[2]);
            split_f16(res.w, h[3], l[3]);
            reinterpret_cast<uint2*>(g_xh + (size_t)warp * 128)[lane] =
                *reinterpret_cast<uint2*>(h);
            reinterpret_cast<uint2*>(g_xl + (size_t)warp * 128)[lane] =
                *reinterpret_cast<uint2*>(l);
        }
    } else {
        float2 acc = make_float2(0.f, 0.f);
        int j = beg;
        for (; j + 3 < end; j += 4) {
            int s0 = g_csr_src[j], s1 = g_csr_src[j + 1];
            int s2 = g_csr_src[j + 2], s3 = g_csr_src[j + 3];
            float2 v0 = reinterpret_cast<const float2*>(g_z + (size_t)s0 * RS)[lane];
            float2 v1 = reinterpret_cast<const float2*>(g_z + (size_t)s1 * RS)[lane];
            float2 v2 = reinterpret_cast<const float2*>(g_z + (size_t)s2 * RS)[lane];
            float2 v3 = reinterpret_cast<const float2*>(g_z + (size_t)s3 * RS)[lane];
            acc.x += (v0.x + v1.x) + (v2.x + v3.x);
            acc.y += (v0.y + v1.y) + (v2.y + v3.y);
        }
        for (; j < end; j++) {
            int s0 = g_csr_src[j];
            float2 v0 = reinterpret_cast<const float2*>(g_z + (size_t)s0 * RS)[lane];
            acc.x += v0.x; acc.y += v0.y;
        }
        float2 zr = reinterpret_cast<const float2*>(g_z + (size_t)warp * RS + O)[lane];
        float2 bb = reinterpret_cast<const float2*>(b)[lane];
        float2 res;
        res.x = acc.x * inv + zr.x + bb.x;
        res.y = acc.y * inv + zr.y + bb.y;
        unsigned short h[2], l[2];
        split_f16(res.x, h[0], l[0]);
        split_f16(res.y, h[1], l[1]);
        reinterpret_cast<unsigned int*>(g_xh + (size_t)warp * 128 + 64)[lane] =
            *reinterpret_cast<unsigned int*>(h);
        reinterpret_cast<unsigned int*>(g_xl + (size_t)warp * 128 + 64)[lane] =
            *reinterpret_cast<unsigned int*>(l);
        reinterpret_cast<float2*>(g_hf + (size_t)warp * 64)[lane] = res;
    }
}

// gather-mean over g_hf (64-wide) -> fp16 split into LEFT half of A buffer.
__global__ void gather_mean_split_kernel() {
    int warp = (blockIdx.x * blockDim.x + threadIdx.x) >> 5;
    int lane = threadIdx.x & 31;
    if (warp >= NNODES) return;
    int beg = g_rowptr[warp];
    int end = g_rowptr[warp + 1];
    float inv = g_inv[warp];

    float2 acc = make_float2(0.f, 0.f);
    int j = beg;
    for (; j + 3 < end; j += 4) {
        int s0 = g_csr_src[j], s1 = g_csr_src[j + 1];
        int s2 = g_csr_src[j + 2], s3 = g_csr_src[j + 3];
        float2 v0 = reinterpret_cast<const float2*>(g_hf + (size_t)s0 * 64)[lane];
        float2 v1 = reinterpret_cast<const float2*>(g_hf + (size_t)s1 * 64)[lane];
        float2 v2 = reinterpret_cast<const float2*>(g_hf + (size_t)s2 * 64)[lane];
        float2 v3 = reinterpret_cast<const float2*>(g_hf + (size_t)s3 * 64)[lane];
        acc.x += (v0.x + v1.x) + (v2.x + v3.x);
        acc.y += (v0.y + v1.y) + (v2.y + v3.y);
    }
    for (; j < end; j++) {
        int s0 = g_csr_src[j];
        float2 v0 = reinterpret_cast<const float2*>(g_hf + (size_t)s0 * 64)[lane];
        acc.x += v0.x; acc.y += v0.y;
    }
    acc.x *= inv; acc.y *= inv;
    unsigned short h[2], l[2];
    split_f16(acc.x, h[0], l[0]);
    split_f16(acc.y, h[1], l[1]);
    reinterpret_cast<unsigned int*>(g_xh + (size_t)warp * 128)[lane] =
        *reinterpret_cast<unsigned int*>(h);
    reinterpret_cast<unsigned int*>(g_xl + (size_t)warp * 128)[lane] =
        *reinterpret_cast<unsigned int*>(l);
}

// ======================= launch =======================
extern "C" void kernel_launch(void* const* d_in, const int* in_sizes, int n_in,
                              void* d_out, int out_size) {
    const float* x   = (const float*)d_in[0];
    const int*   ei  = (const int*)d_in[1];   // int32 (JAX x64 disabled)
    const float* Wl1 = (const float*)d_in[2];
    const float* b1  = (const float*)d_in[3];
    const float* Wr1 = (const float*)d_in[4];
    const float* Wl2 = (const float*)d_in[5];
    const float* b2  = (const float*)d_in[6];
    const float* Wr2 = (const float*)d_in[7];
    const float* Wl3 = (const float*)d_in[8];
    const float* b3  = (const float*)d_in[9];
    const float* Wr3 = (const float*)d_in[10];
    float* out = (float*)d_out;

    const int TB = 256;
    const int MT = NPAD / 128;                    // 391 M-tiles
    const int GW = (NNODES * 32 + TB - 1) / TB;   // gather: warp/node

    // Fork a side stream for the tensor-bound chain; CSR build (L2/atomic-
    // bound) runs concurrently on the main (capture) stream.
    cudaStream_t s1;
    cudaStreamCreate(&s1);
    cudaEvent_t evFork, evJoin;
    cudaEventCreateWithFlags(&evFork, cudaEventDisableTiming);
    cudaEventCreateWithFlags(&evJoin, cudaEventDisableTiming);

    cudaEventRecord(evFork, 0);
    cudaStreamWaitEvent(s1, evFork, 0);

    // ---- side stream: conversions + layer-1 GEMM ----
    conv_x_kernel<<<(NPAD * 128 / 8 + TB - 1) / TB, TB, 0, s1>>>(x);
    conv_w_kernel<128, 128, 1><<<(2 * 128 * 128 / 8 + TB - 1) / TB, TB, 0, s1>>>(Wl1, Wr1);
    conv_w_kernel<128, 64, 2><<<(2 * 64 * 128 / 8 + TB - 1) / TB, TB, 0, s1>>>(Wl2, Wr2);
    conv_wcat_kernel<64, 128, 3><<<(128 * 128 / 8 + TB - 1) / TB, TB, 0, s1>>>(Wl3, Wr3);
    mma_gemm_kernel<128, 256, 0, 1><<<dim3(MT, 4), 256, 0, s1>>>(nullptr, nullptr);
    cudaEventRecord(evJoin, s1);

    // ---- main stream: CSR build (concurrent) ----
    zero_deg_kernel<<<(NNODES + TB - 1) / TB, TB>>>();
    count_kernel<<<(NEDGES + TB - 1) / TB, TB>>>(ei);
    scan_kernel<<<1, SCAN_T>>>();
    fill_kernel<<<(NEDGES + TB - 1) / TB, TB>>>(ei);

    cudaStreamWaitEvent(0, evJoin, 0);   // join: gather needs CSR + z1

    // Layer 1 epilogue: h1 -> A[n][0..128)
    gather_add_kernel<128, 1><<<GW, TB>>>(b1, nullptr);

    // Layer 2: I=128, N2=128
    mma_gemm_kernel<128, 128, 0, 2><<<dim3(MT, 2), 256>>>(nullptr, nullptr);
    gather_add_kernel<64, 2><<<GW, TB>>>(b2, nullptr);    // h2 -> A[n][64..128) + g_hf

    // Layer 3: A = [mean(h2) | h2]; GEMM writes d_out + b3
    gather_mean_split_kernel<<<GW, TB>>>();               // mean -> A[n][0..64)
    mma_gemm_kernel<128, 128, 1, 3><<<dim3(MT, 2), 256>>>(b3, out);
}

// round 16
// speedup vs baseline: 1.9152x; 1.0504x over previous
#include <cuda_runtime.h>
#include <cuda_fp16.h>
#include <cstdint>

#define NNODES 50000
#define NPAD   50048           // 391 * 128
#define NEDGES 800000
#define SCAN_T 1024

// ======================= device-global scratch =======================
__device__ __align__(16) int   g_deg[NNODES];
__device__ __align__(16) int   g_rowptr[NNODES + 1];
__device__ __align__(16) int   g_cursor[NNODES];
__device__ __align__(16) int   g_csr_src[NEDGES];
__device__ __align__(16) float g_inv[NNODES];
// z split by role: aggregated half (fp16, gathered per-edge) / root half (f32)
__device__ __align__(16) unsigned short g_zl[NNODES * 128];  // fp16
__device__ __align__(16) float          g_zr[NNODES * 128];  // f32
__device__ __align__(16) unsigned short g_hfh[NNODES * 64];  // fp16 h2 (layer-3 mean src)
// fp16 hi/lo splits; A layout stays [NPAD x 128] for ALL layers
__device__ __align__(16) unsigned short g_xh[NPAD * 128];
__device__ __align__(16) unsigned short g_xl[NPAD * 128];
// per-layer weight buffers
__device__ __align__(16) unsigned short g_w1h[256 * 128];
__device__ __align__(16) unsigned short g_w1l[256 * 128];
__device__ __align__(16) unsigned short g_w2h[128 * 128];
__device__ __align__(16) unsigned short g_w2l[128 * 128];
__device__ __align__(16) unsigned short g_w3h[128 * 128];
__device__ __align__(16) unsigned short g_w3l[128 * 128];

template <int WSEL>
__device__ __forceinline__ const unsigned short* wsel_h() {
    if (WSEL == 1) return g_w1h;
    if (WSEL == 2) return g_w2h;
    return g_w3h;
}
template <int WSEL>
__device__ __forceinline__ const unsigned short* wsel_l() {
    if (WSEL == 1) return g_w1l;
    if (WSEL == 2) return g_w2l;
    return g_w3l;
}
template <int WSEL>
__device__ __forceinline__ unsigned short* wsel_h_mut() {
    if (WSEL == 1) return g_w1h;
    if (WSEL == 2) return g_w2h;
    return g_w3h;
}
template <int WSEL>
__device__ __forceinline__ unsigned short* wsel_l_mut() {
    if (WSEL == 1) return g_w1l;
    if (WSEL == 2) return g_w2l;
    return g_w3l;
}

// ======================= CSR build =======================
__global__ void zero_deg_kernel() {
    int i = blockIdx.x * blockDim.x + threadIdx.x;
    if (i < NNODES) g_deg[i] = 0;
}
__global__ void count_kernel(const int* __restrict__ ei) {
    int e = blockIdx.x * blockDim.x + threadIdx.x;
    if (e < NEDGES) atomicAdd(&g_deg[ei[NEDGES + e]], 1);
}
__global__ void scan_kernel() {
    __shared__ int partial[SCAN_T];
    const int t = threadIdx.x;
    const int CH = (NNODES + SCAN_T - 1) / SCAN_T;
    const int base = t * CH;
    int s = 0;
    for (int i = 0; i < CH; i++) {
        int idx = base + i;
        if (idx < NNODES) s += g_deg[idx];
    }
    partial[t] = s;
    __syncthreads();
    for (int off = 1; off < SCAN_T; off <<= 1) {
        int add = (t >= off) ? partial[t - off] : 0;
        __syncthreads();
        partial[t] += add;
        __syncthreads();
    }
    int run = (t == 0) ? 0 : partial[t - 1];
    for (int i = 0; i < CH; i++) {
        int idx = base + i;
        if (idx < NNODES) {
            g_rowptr[idx] = run;
            g_cursor[idx] = run;
            g_inv[idx] = 1.0f / fmaxf((float)g_deg[idx], 1.0f);
            run += g_deg[idx];
        }
    }
    if (t == SCAN_T - 1) g_rowptr[NNODES] = partial[SCAN_T - 1];
}
__global__ void fill_kernel(const int* __restrict__ ei) {
    int e = blockIdx.x * blockDim.x + threadIdx.x;
    if (e < NEDGES) {
        int dst = ei[NEDGES + e];
        int slot = atomicAdd(&g_cursor[dst], 1);
        g_csr_src[slot] = ei[e];
    }
}

// ======================= fp16 split helpers =======================
union U4H8 { uint4 v; unsigned short u16[8]; };

__device__ __forceinline__ void split_f16(float f, unsigned short& hi, unsigned short& lo) {
    __half h = __float2half_rn(f);
    hi = __half_as_ushort(h);
    __half l = __float2half_rn(f - __half2float(h));
    lo = __half_as_ushort(l);
}

// input x -> g_xh/g_xl [NPAD x 128], pad rows zeroed (stay zero all run).
__global__ void conv_x_kernel(const float* __restrict__ x) {
    int t = blockIdx.x * blockDim.x + threadIdx.x;
    if (t >= NPAD * 128 / 8) return;
    int base = t * 8;
    int row = base / 128;
    U4H8 hi, lo;
    hi.v = make_uint4(0, 0, 0, 0);
    lo.v = make_uint4(0, 0, 0, 0);
    if (row < NNODES) {
        const float4* src = reinterpret_cast<const float4*>(x + base);
        float4 f0 = src[0], f1 = src[1];
        float f[8] = {f0.x, f0.y, f0.z, f0.w, f1.x, f1.y, f1.z, f1.w};
#pragma unroll
        for (int i = 0; i < 8; i++) split_f16(f[i], hi.u16[i], lo.u16[i]);
    }
    reinterpret_cast<uint4*>(g_xh)[t] = hi.v;
    reinterpret_cast<uint4*>(g_xl)[t] = lo.v;
}

// W = [Wl;Wr] stacked (2O rows x I) -> weight buffer WSEL
template <int I, int O, int WSEL>
__global__ void conv_w_kernel(const float* __restrict__ Wl,
                              const float* __restrict__ Wr) {
    int t = blockIdx.x * blockDim.x + threadIdx.x;
    if (t >= 2 * O * I / 8) return;
    int base = t * 8;
    int j = base / I;
    int k = base % I;
    const float* wrow = (j < O) ? (Wl + (size_t)j * I) : (Wr + (size_t)(j - O) * I);
    const float4* src = reinterpret_cast<const float4*>(wrow + k);
    float4 f0 = src[0], f1 = src[1];
    float f[8] = {f0.x, f0.y, f0.z, f0.w, f1.x, f1.y, f1.z, f1.w};
    U4H8 hi, lo;
#pragma unroll
    for (int i = 0; i < 8; i++) split_f16(f[i], hi.u16[i], lo.u16[i]);
    reinterpret_cast<uint4*>(wsel_h_mut<WSEL>())[t] = hi.v;
    reinterpret_cast<uint4*>(wsel_l_mut<WSEL>())[t] = lo.v;
}

// W_cat = [Wl | Wr] side-by-side (O rows x 2*IH cols) -> weight buffer WSEL
template <int IH, int O, int WSEL>
__global__ void conv_wcat_kernel(const float* __restrict__ Wl,
                                 const float* __restrict__ Wr) {
    constexpr int I = 2 * IH;
    int t = blockIdx.x * blockDim.x + threadIdx.x;
    if (t >= O * I / 8) return;
    int base = t * 8;
    int j = base / I;
    int k = base % I;
    const float* src = (k < IH) ? (Wl + (size_t)j * IH + k)
                                : (Wr + (size_t)j * IH + (k - IH));
    const float4* s4 = reinterpret_cast<const float4*>(src);
    float4 f0 = s4[0], f1 = s4[1];
    float f[8] = {f0.x, f0.y, f0.z, f0.w, f1.x, f1.y, f1.z, f1.w};
    U4H8 hi, lo;
#pragma unroll
    for (int i = 0; i < 8; i++) split_f16(f[i], hi.u16[i], lo.u16[i]);
    reinterpret_cast<uint4*>(wsel_h_mut<WSEL>())[t] = hi.v;
    reinterpret_cast<uint4*>(wsel_l_mut<WSEL>())[t] = lo.v;
}

// ======================= split-fp16 mma.sync GEMM =======================
// z = A @ W^T via D = Ah*Bh + Ah*Bl + Al*Bh (fp32 acc), m16n8k16.
// OMODE 0: cols [0,O) -> g_zl fp16; cols [O,2O) -> g_zr f32 (no bias).
// OMODE 1: write outp f32 rows of width N2 with bias.
template <int I, int N2, int OMODE, int WSEL>
__global__ __launch_bounds__(256)
void mma_gemm_kernel(const float* __restrict__ bias, float* __restrict__ outp) {
    __shared__ __align__(16) unsigned int ash[128][12];
    __shared__ __align__(16) unsigned int asl[128][12];
    __shared__ __align__(16) unsigned int bsh[64][12];
    __shared__ __align__(16) unsigned int bsl[64][12];

    const int t    = threadIdx.x;
    const int w    = t >> 5;
    const int lane = t & 31;
    const int gid  = lane >> 2;
    const int tig  = lane & 3;
    const int m0   = blockIdx.x * 128;
    const int n0   = blockIdx.y * 64;
    const int wrow = w * 16;
    constexpr int O = N2 / 2;

    float acc[8][4];
#pragma unroll
    for (int j = 0; j < 8; j++)
#pragma unroll
        for (int c = 0; c < 4; c++) acc[j][c] = 0.0f;

    const int arow = t >> 1, aq = t & 1;
    const int tb = t & 127;
    const int brow = tb >> 1, bq = tb & 1;

    for (int k0 = 0; k0 < I; k0 += 16) {
        {
            uint4 vh = *reinterpret_cast<const uint4*>(
                g_xh + (size_t)(m0 + arow) * I + k0 + 8 * aq);
            uint4 vl = *reinterpret_cast<const uint4*>(
                g_xl + (size_t)(m0 + arow) * I + k0 + 8 * aq);
            *reinterpret_cast<uint4*>(&ash[arow][4 * aq]) = vh;
            *reinterpret_cast<uint4*>(&asl[arow][4 * aq]) = vl;
            const unsigned short* W = (t < 128) ? wsel_h<WSEL>() : wsel_l<WSEL>();
            uint4 vb = *reinterpret_cast<const uint4*>(
                W + (size_t)(n0 + brow) * I + k0 + 8 * bq);
            if (t < 128)
                *reinterpret_cast<uint4*>(&bsh[brow][4 * bq]) = vb;
            else
                *reinterpret_cast<uint4*>(&bsl[brow][4 * bq]) = vb;
        }
        __syncthreads();
        {
            unsigned int ah0 = ash[wrow + gid][tig];
            unsigned int ah1 = ash[wrow + gid + 8][tig];
            unsigned int ah2 = ash[wrow + gid][tig + 4];
            unsigned int ah3 = ash[wrow + gid + 8][tig + 4];
            unsigned int al0 = asl[wrow + gid][tig];
            unsigned int al1 = asl[wrow + gid + 8][tig];
            unsigned int al2 = asl[wrow + gid][tig + 4];
            unsigned int al3 = asl[wrow + gid + 8][tig + 4];
#pragma unroll
            for (int j = 0; j < 8; j++) {
                unsigned int bh0 = bsh[8 * j + gid][tig];
                unsigned int bh1 = bsh[8 * j + gid][tig + 4];
                unsigned int bl0 = bsl[8 * j + gid][tig];
                unsigned int bl1 = bsl[8 * j + gid][tig + 4];
                asm volatile(
                    "mma.sync.aligned.m16n8k16.row.col.f32.f16.f16.f32 "
                    "{%0,%1,%2,%3}, {%4,%5,%6,%7}, {%8,%9}, {%0,%1,%2,%3};"
                    : "+f"(acc[j][0]), "+f"(acc[j][1]),
                      "+f"(acc[j][2]), "+f"(acc[j][3])
                    : "r"(ah0), "r"(ah1), "r"(ah2), "r"(ah3), "r"(bh0), "r"(bh1));
                asm volatile(
                    "mma.sync.aligned.m16n8k16.row.col.f32.f16.f16.f32 "
                    "{%0,%1,%2,%3}, {%4,%5,%6,%7}, {%8,%9}, {%0,%1,%2,%3};"
                    : "+f"(acc[j][0]), "+f"(acc[j][1]),
                      "+f"(acc[j][2]), "+f"(acc[j][3])
                    : "r"(ah0), "r"(ah1), "r"(ah2), "r"(ah3), "r"(bl0), "r"(bl1));
                asm volatile(
                    "mma.sync.aligned.m16n8k16.row.col.f32.f16.f16.f32 "
                    "{%0,%1,%2,%3}, {%4,%5,%6,%7}, {%8,%9}, {%0,%1,%2,%3};"
                    : "+f"(acc[j][0]), "+f"(acc[j][1]),
                      "+f"(acc[j][2]), "+f"(acc[j][3])
                    : "r"(al0), "r"(al1), "r"(al2), "r"(al3), "r"(bh0), "r"(bh1));
            }
        }
        __syncthreads();
    }

    const int node0 = m0 + wrow + gid;
    const int node1 = node0 + 8;
#pragma unroll
    for (int j = 0; j < 8; j++) {
        int col = n0 + 8 * j + 2 * tig;
        if (OMODE == 0) {
            if (n0 < O) {   // aggregated half -> fp16 (uniform per block: BN=64 <= O)
                if (node0 < NNODES)
                    *reinterpret_cast<__half2*>(g_zl + (size_t)node0 * O + col) =
                        __floats2half2_rn(acc[j][0], acc[j][1]);
                if (node1 < NNODES)
                    *reinterpret_cast<__half2*>(g_zl + (size_t)node1 * O + col) =
                        __floats2half2_rn(acc[j][2], acc[j][3]);
            } else {        // root half -> f32
                int c2 = col - O;
                if (node0 < NNODES)
                    *reinterpret_cast<float2*>(g_zr + (size_t)node0 * O + c2) =
                        make_float2(acc[j][0], acc[j][1]);
                if (node1 < NNODES)
                    *reinterpret_cast<float2*>(g_zr + (size_t)node1 * O + c2) =
                        make_float2(acc[j][2], acc[j][3]);
            }
        } else {
            float bx = bias[col], by = bias[col + 1];
            if (node0 < NNODES)
                *reinterpret_cast<float2*>(outp + (size_t)node0 * N2 + col) =
                    make_float2(acc[j][0] + bx, acc[j][1] + by);
            if (node1 < NNODES)
                *reinterpret_cast<float2*>(outp + (size_t)node1 * N2 + col) =
                    make_float2(acc[j][2] + bx, acc[j][3] + by);
        }
    }
}

// ======================= gather-add (fp16 z_l, unroll 8) =======================
// h[n] = inv[n]*sum zl[src] + zr[n] + b.
// MODE 1 (O=128): fp16 split -> g_xh/g_xl [n][128].
// MODE 2 (O=64):  fp16 split -> RIGHT half of g_xh/g_xl [n][128], fp16 -> g_hfh.
template <int O, int MODE>
__global__ void gather_add_kernel(const float* __restrict__ b) {
    int warp = (blockIdx.x * blockDim.x + threadIdx.x) >> 5;
    int lane = threadIdx.x & 31;
    if (warp >= NNODES) return;
    int beg = g_rowptr[warp];
    int end = g_rowptr[warp + 1];
    float inv = g_inv[warp];

    if (O == 128) {
        float4 acc = make_float4(0.f, 0.f, 0.f, 0.f);
        int j = beg;
        for (; j + 7 < end; j += 8) {
            uint2 v[8];
#pragma unroll
            for (int u = 0; u < 8; u++) {
                int s = g_csr_src[j + u];
                v[u] = reinterpret_cast<const uint2*>(g_zl + (size_t)s * 128)[lane];
            }
#pragma unroll
            for (int u = 0; u < 8; u++) {
                float2 f0 = __half22float2(*reinterpret_cast<__half2*>(&v[u].x));
                float2 f1 = __half22float2(*reinterpret_cast<__half2*>(&v[u].y));
                acc.x += f0.x; acc.y += f0.y; acc.z += f1.x; acc.w += f1.y;
            }
        }
        for (; j < end; j++) {
            int s = g_csr_src[j];
            uint2 v = reinterpret_cast<const uint2*>(g_zl + (size_t)s * 128)[lane];
            float2 f0 = __half22float2(*reinterpret_cast<__half2*>(&v.x));
            float2 f1 = __half22float2(*reinterpret_cast<__half2*>(&v.y));
            acc.x += f0.x; acc.y += f0.y; acc.z += f1.x; acc.w += f1.y;
        }
        float4 zr = reinterpret_cast<const float4*>(g_zr + (size_t)warp * 128)[lane];
        float4 bb = reinterpret_cast<const float4*>(b)[lane];
        float4 res;
        res.x = acc.x * inv + zr.x + bb.x;
        res.y = acc.y * inv + zr.y + bb.y;
        res.z = acc.z * inv + zr.z + bb.z;
        res.w = acc.w * inv + zr.w + bb.w;
        unsigned short h[4], l[4];
        split_f16(res.x, h[0], l[0]);
        split_f16(res.y, h[1], l[1]);
        split_f16(res.z, h[2], l[2]);
        split_f16(res.w, h[3], l[3]);
        reinterpret_cast<uint2*>(g_xh + (size_t)warp * 128)[lane] =
            *reinterpret_cast<uint2*>(h);
        reinterpret_cast<uint2*>(g_xl + (size_t)warp * 128)[lane] =
            *reinterpret_cast<uint2*>(l);
    } else {
        float2 acc = make_float2(0.f, 0.f);
        int j = beg;
        for (; j + 7 < end; j += 8) {
            unsigned int v[8];
#pragma unroll
            for (int u = 0; u < 8; u++) {
                int s = g_csr_src[j + u];
                v[u] = reinterpret_cast<const unsigned int*>(g_zl + (size_t)s * 64)[lane];
            }
#pragma unroll
            for (int u = 0; u < 8; u++) {
                float2 f = __half22float2(*reinterpret_cast<__half2*>(&v[u]));
                acc.x += f.x; acc.y += f.y;
            }
        }
        for (; j < end; j++) {
            int s = g_csr_src[j];
            unsigned int v = reinterpret_cast<const unsigned int*>(g_zl + (size_t)s * 64)[lane];
            float2 f = __half22float2(*reinterpret_cast<__half2*>(&v));
            acc.x += f.x; acc.y += f.y;
        }
        float2 zr = reinterpret_cast<const float2*>(g_zr + (size_t)warp * 64)[lane];
        float2 bb = reinterpret_cast<const float2*>(b)[lane];
        float2 res;
        res.x = acc.x * inv + zr.x + bb.x;
        res.y = acc.y * inv + zr.y + bb.y;
        unsigned short h[2], l[2];
        split_f16(res.x, h[0], l[0]);
        split_f16(res.y, h[1], l[1]);
        reinterpret_cast<unsigned int*>(g_xh + (size_t)warp * 128 + 64)[lane] =
            *reinterpret_cast<unsigned int*>(h);
        reinterpret_cast<unsigned int*>(g_xl + (size_t)warp * 128 + 64)[lane] =
            *reinterpret_cast<unsigned int*>(l);
        *reinterpret_cast<__half2*>(g_hfh + (size_t)warp * 64 + lane * 2) =
            __floats2half2_rn(res.x, res.y);
    }
}

// gather-mean over g_hfh (fp16, 64-wide) -> fp16 split into LEFT half of A.
__global__ void gather_mean_split_kernel() {
    int warp = (blockIdx.x * blockDim.x + threadIdx.x) >> 5;
    int lane = threadIdx.x & 31;
    if (warp >= NNODES) return;
    int beg = g_rowptr[warp];
    int end = g_rowptr[warp + 1];
    float inv = g_inv[warp];

    float2 acc = make_float2(0.f, 0.f);
    int j = beg;
    for (; j + 7 < end; j += 8) {
        unsigned int v[8];
#pragma unroll
        for (int u = 0; u < 8; u++) {
            int s = g_csr_src[j + u];
            v[u] = reinterpret_cast<const unsigned int*>(g_hfh + (size_t)s * 64)[lane];
        }
#pragma unroll
        for (int u = 0; u < 8; u++) {
            float2 f = __half22float2(*reinterpret_cast<__half2*>(&v[u]));
            acc.x += f.x; acc.y += f.y;
        }
    }
    for (; j < end; j++) {
        int s = g_csr_src[j];
        unsigned int v = reinterpret_cast<const unsigned int*>(g_hfh + (size_t)s * 64)[lane];
        float2 f = __half22float2(*reinterpret_cast<__half2*>(&v));
        acc.x += f.x; acc.y += f.y;
    }
    acc.x *= inv; acc.y *= inv;
    unsigned short h[2], l[2];
    split_f16(acc.x, h[0], l[0]);
    split_f16(acc.y, h[1], l[1]);
    reinterpret_cast<unsigned int*>(g_xh + (size_t)warp * 128)[lane] =
        *reinterpret_cast<unsigned int*>(h);
    reinterpret_cast<unsigned int*>(g_xl + (size_t)warp * 128)[lane] =
        *reinterpret_cast<unsigned int*>(l);
}

// ======================= launch =======================
extern "C" void kernel_launch(void* const* d_in, const int* in_sizes, int n_in,
                              void* d_out, int out_size) {
    const float* x   = (const float*)d_in[0];
    const int*   ei  = (const int*)d_in[1];   // int32 (JAX x64 disabled)
    const float* Wl1 = (const float*)d_in[2];
    const float* b1  = (const float*)d_in[3];
    const float* Wr1 = (const float*)d_in[4];
    const float* Wl2 = (const float*)d_in[5];
    const float* b2  = (const float*)d_in[6];
    const float* Wr2 = (const float*)d_in[7];
    const float* Wl3 = (const float*)d_in[8];
    const float* b3  = (const float*)d_in[9];
    const float* Wr3 = (const float*)d_in[10];
    float* out = (float*)d_out;

    const int TB = 256;
    const int MT = NPAD / 128;                    // 391 M-tiles
    const int GW = (NNODES * 32 + TB - 1) / TB;   // gather: warp/node

    // Fork a side stream for the tensor-bound chain; CSR build runs
    // concurrently on the main (capture) stream.
    cudaStream_t s1;
    cudaStreamCreate(&s1);
    cudaEvent_t evFork, evJoin;
    cudaEventCreateWithFlags(&evFork, cudaEventDisableTiming);
    cudaEventCreateWithFlags(&evJoin, cudaEventDisableTiming);

    cudaEventRecord(evFork, 0);
    cudaStreamWaitEvent(s1, evFork, 0);

    // ---- side stream: conversions + layer-1 GEMM ----
    conv_x_kernel<<<(NPAD * 128 / 8 + TB - 1) / TB, TB, 0, s1>>>(x);
    conv_w_kernel<128, 128, 1><<<(2 * 128 * 128 / 8 + TB - 1) / TB, TB, 0, s1>>>(Wl1, Wr1);
    conv_w_kernel<128, 64, 2><<<(2 * 64 * 128 / 8 + TB - 1) / TB, TB, 0, s1>>>(Wl2, Wr2);
    conv_wcat_kernel<64, 128, 3><<<(128 * 128 / 8 + TB - 1) / TB, TB, 0, s1>>>(Wl3, Wr3);
    mma_gemm_kernel<128, 256, 0, 1><<<dim3(MT, 4), 256, 0, s1>>>(nullptr, nullptr);
    cudaEventRecord(evJoin, s1);

    // ---- main stream: CSR build (concurrent) ----
    zero_deg_kernel<<<(NNODES + TB - 1) / TB, TB>>>();
    count_kernel<<<(NEDGES + TB - 1) / TB, TB>>>(ei);
    scan_kernel<<<1, SCAN_T>>>();
    fill_kernel<<<(NEDGES + TB - 1) / TB, TB>>>(ei);

    cudaStreamWaitEvent(0, evJoin, 0);   // join: gather needs CSR + z1

    // Layer 1 epilogue: h1 -> A[n][0..128)
    gather_add_kernel<128, 1><<<GW, TB>>>(b1);

    // Layer 2: I=128, N2=128
    mma_gemm_kernel<128, 128, 0, 2><<<dim3(MT, 2), 256>>>(nullptr, nullptr);
    gather_add_kernel<64, 2><<<GW, TB>>>(b2);             // h2 -> A[n][64..128) + g_hfh

    // Layer 3: A = [mean(h2) | h2]; GEMM writes d_out + b3
    gather_mean_split_kernel<<<GW, TB>>>();               // mean -> A[n][0..64)
    mma_gemm_kernel<128, 128, 1, 3><<<dim3(MT, 2), 256>>>(b3, out);
}

// round 17
// speedup vs baseline: 1.9771x; 1.0323x over previous
#include <cuda_runtime.h>
#include <cuda_fp16.h>
#include <cstdint>

#define NNODES 50000
#define NPAD   50048           // 391 * 128
#define NEDGES 800000
#define SCAN_T 1024

// ======================= device-global scratch =======================
__device__ __align__(16) int   g_deg[NNODES];
__device__ __align__(16) int   g_rowptr[NNODES + 1];
__device__ __align__(16) int   g_cursor[NNODES];
__device__ __align__(16) int   g_csr_src[NEDGES];
__device__ __align__(16) float g_inv[NNODES];
// z split by role: aggregated half (fp16, gathered per-edge) / root half (f32)
__device__ __align__(16) unsigned short g_zl[NNODES * 128];  // fp16
__device__ __align__(16) float          g_zr[NNODES * 128];  // f32
__device__ __align__(16) unsigned short g_hfh[NNODES * 64];  // fp16 h2 (layer-3 mean src)
// fp16 hi/lo splits; A layout stays [NPAD x 128] for ALL layers
__device__ __align__(16) unsigned short g_xh[NPAD * 128];
__device__ __align__(16) unsigned short g_xl[NPAD * 128];
// per-layer weight buffers
__device__ __align__(16) unsigned short g_w1h[256 * 128];
__device__ __align__(16) unsigned short g_w1l[256 * 128];
__device__ __align__(16) unsigned short g_w2h[128 * 128];
__device__ __align__(16) unsigned short g_w2l[128 * 128];
__device__ __align__(16) unsigned short g_w3h[128 * 128];
__device__ __align__(16) unsigned short g_w3l[128 * 128];

template <int WSEL>
__device__ __forceinline__ const unsigned short* wsel_h() {
    if (WSEL == 1) return g_w1h;
    if (WSEL == 2) return g_w2h;
    return g_w3h;
}
template <int WSEL>
__device__ __forceinline__ const unsigned short* wsel_l() {
    if (WSEL == 1) return g_w1l;
    if (WSEL == 2) return g_w2l;
    return g_w3l;
}
template <int WSEL>
__device__ __forceinline__ unsigned short* wsel_h_mut() {
    if (WSEL == 1) return g_w1h;
    if (WSEL == 2) return g_w2h;
    return g_w3h;
}
template <int WSEL>
__device__ __forceinline__ unsigned short* wsel_l_mut() {
    if (WSEL == 1) return g_w1l;
    if (WSEL == 2) return g_w2l;
    return g_w3l;
}

// ======================= CSR build =======================
__global__ void zero_deg_kernel() {
    int i = blockIdx.x * blockDim.x + threadIdx.x;
    if (i < NNODES) g_deg[i] = 0;
}
__global__ void count_kernel(const int* __restrict__ ei) {
    int e = blockIdx.x * blockDim.x + threadIdx.x;
    if (e < NEDGES) atomicAdd(&g_deg[ei[NEDGES + e]], 1);
}
__global__ void scan_kernel() {
    __shared__ int partial[SCAN_T];
    const int t = threadIdx.x;
    const int CH = (NNODES + SCAN_T - 1) / SCAN_T;
    const int base = t * CH;
    int s = 0;
    for (int i = 0; i < CH; i++) {
        int idx = base + i;
        if (idx < NNODES) s += g_deg[idx];
    }
    partial[t] = s;
    __syncthreads();
    for (int off = 1; off < SCAN_T; off <<= 1) {
        int add = (t >= off) ? partial[t - off] : 0;
        __syncthreads();
        partial[t] += add;
        __syncthreads();
    }
    int run = (t == 0) ? 0 : partial[t - 1];
    for (int i = 0; i < CH; i++) {
        int idx = base + i;
        if (idx < NNODES) {
            g_rowptr[idx] = run;
            g_cursor[idx] = run;
            g_inv[idx] = 1.0f / fmaxf((float)g_deg[idx], 1.0f);
            run += g_deg[idx];
        }
    }
    if (t == SCAN_T - 1) g_rowptr[NNODES] = partial[SCAN_T - 1];
}
__global__ void fill_kernel(const int* __restrict__ ei) {
    int e = blockIdx.x * blockDim.x + threadIdx.x;
    if (e < NEDGES) {
        int dst = ei[NEDGES + e];
        int slot = atomicAdd(&g_cursor[dst], 1);
        g_csr_src[slot] = ei[e];
    }
}

// ======================= fp16 split helpers =======================
union U4H8 { uint4 v; unsigned short u16[8]; };

__device__ __forceinline__ void split_f16(float f, unsigned short& hi, unsigned short& lo) {
    __half h = __float2half_rn(f);
    hi = __half_as_ushort(h);
    __half l = __float2half_rn(f - __half2float(h));
    lo = __half_as_ushort(l);
}

// input x -> g_xh/g_xl [NPAD x 128], pad rows zeroed (stay zero all run).
__global__ void conv_x_kernel(const float* __restrict__ x) {
    int t = blockIdx.x * blockDim.x + threadIdx.x;
    if (t >= NPAD * 128 / 8) return;
    int base = t * 8;
    int row = base / 128;
    U4H8 hi, lo;
    hi.v = make_uint4(0, 0, 0, 0);
    lo.v = make_uint4(0, 0, 0, 0);
    if (row < NNODES) {
        const float4* src = reinterpret_cast<const float4*>(x + base);
        float4 f0 = src[0], f1 = src[1];
        float f[8] = {f0.x, f0.y, f0.z, f0.w, f1.x, f1.y, f1.z, f1.w};
#pragma unroll
        for (int i = 0; i < 8; i++) split_f16(f[i], hi.u16[i], lo.u16[i]);
    }
    reinterpret_cast<uint4*>(g_xh)[t] = hi.v;
    reinterpret_cast<uint4*>(g_xl)[t] = lo.v;
}

// W = [Wl;Wr] stacked (2O rows x I) -> weight buffer WSEL
template <int I, int O, int WSEL>
__global__ void conv_w_kernel(const float* __restrict__ Wl,
                              const float* __restrict__ Wr) {
    int t = blockIdx.x * blockDim.x + threadIdx.x;
    if (t >= 2 * O * I / 8) return;
    int base = t * 8;
    int j = base / I;
    int k = base % I;
    const float* wrow = (j < O) ? (Wl + (size_t)j * I) : (Wr + (size_t)(j - O) * I);
    const float4* src = reinterpret_cast<const float4*>(wrow + k);
    float4 f0 = src[0], f1 = src[1];
    float f[8] = {f0.x, f0.y, f0.z, f0.w, f1.x, f1.y, f1.z, f1.w};
    U4H8 hi, lo;
#pragma unroll
    for (int i = 0; i < 8; i++) split_f16(f[i], hi.u16[i], lo.u16[i]);
    reinterpret_cast<uint4*>(wsel_h_mut<WSEL>())[t] = hi.v;
    reinterpret_cast<uint4*>(wsel_l_mut<WSEL>())[t] = lo.v;
}

// W_cat = [Wl | Wr] side-by-side (O rows x 2*IH cols) -> weight buffer WSEL
template <int IH, int O, int WSEL>
__global__ void conv_wcat_kernel(const float* __restrict__ Wl,
                                 const float* __restrict__ Wr) {
    constexpr int I = 2 * IH;
    int t = blockIdx.x * blockDim.x + threadIdx.x;
    if (t >= O * I / 8) return;
    int base = t * 8;
    int j = base / I;
    int k = base % I;
    const float* src = (k < IH) ? (Wl + (size_t)j * IH + k)
                                : (Wr + (size_t)j * IH + (k - IH));
    const float4* s4 = reinterpret_cast<const float4*>(src);
    float4 f0 = s4[0], f1 = s4[1];
    float f[8] = {f0.x, f0.y, f0.z, f0.w, f1.x, f1.y, f1.z, f1.w};
    U4H8 hi, lo;
#pragma unroll
    for (int i = 0; i < 8; i++) split_f16(f[i], hi.u16[i], lo.u16[i]);
    reinterpret_cast<uint4*>(wsel_h_mut<WSEL>())[t] = hi.v;
    reinterpret_cast<uint4*>(wsel_l_mut<WSEL>())[t] = lo.v;
}

// ======================= split-fp16 mma.sync GEMM (BN=128) =======================
// z = A @ W^T via D = Ah*Bh + Ah*Bl + Al*Bh (fp32 acc), m16n8k16.
// Block: 256 thr (8 warps), BM=128 x BN=128, K-chunk=16.
// Warp w: rows 16w..16w+15, ALL 128 cols (16 j-blocks, acc[16][4]).
// OMODE 0: cols [0,O) -> g_zl fp16; cols [O,2O) -> g_zr f32 (no bias).
// OMODE 1: write outp f32 rows of width N2 with bias.
template <int I, int N2, int OMODE, int WSEL>
__global__ __launch_bounds__(256)
void mma_gemm_kernel(const float* __restrict__ bias, float* __restrict__ outp) {
    __shared__ __align__(16) unsigned int ash[128][12];
    __shared__ __align__(16) unsigned int asl[128][12];
    __shared__ __align__(16) unsigned int bsh[128][12];
    __shared__ __align__(16) unsigned int bsl[128][12];

    const int t    = threadIdx.x;
    const int w    = t >> 5;
    const int lane = t & 31;
    const int gid  = lane >> 2;
    const int tig  = lane & 3;
    const int m0   = blockIdx.x * 128;
    const int n0   = blockIdx.y * 128;
    const int wrow = w * 16;
    constexpr int O = N2 / 2;

    float acc[16][4];
#pragma unroll
    for (int j = 0; j < 16; j++)
#pragma unroll
        for (int c = 0; c < 4; c++) acc[j][c] = 0.0f;

    const int arow = t >> 1, aq = t & 1;   // A: 256 uint4 over 256 thr

    for (int k0 = 0; k0 < I; k0 += 16) {
        {
            uint4 vh = *reinterpret_cast<const uint4*>(
                g_xh + (size_t)(m0 + arow) * I + k0 + 8 * aq);
            uint4 vl = *reinterpret_cast<const uint4*>(
                g_xl + (size_t)(m0 + arow) * I + k0 + 8 * aq);
            *reinterpret_cast<uint4*>(&ash[arow][4 * aq]) = vh;
            *reinterpret_cast<uint4*>(&asl[arow][4 * aq]) = vl;
            // B: 128 rows x 16 halves, hi AND lo (each thread: 1 hi + 1 lo uint4)
            uint4 wh = *reinterpret_cast<const uint4*>(
                wsel_h<WSEL>() + (size_t)(n0 + arow) * I + k0 + 8 * aq);
            uint4 wl = *reinterpret_cast<const uint4*>(
                wsel_l<WSEL>() + (size_t)(n0 + arow) * I + k0 + 8 * aq);
            *reinterpret_cast<uint4*>(&bsh[arow][4 * aq]) = wh;
            *reinterpret_cast<uint4*>(&bsl[arow][4 * aq]) = wl;
        }
        __syncthreads();
        {
            unsigned int ah0 = ash[wrow + gid][tig];
            unsigned int ah1 = ash[wrow + gid + 8][tig];
            unsigned int ah2 = ash[wrow + gid][tig + 4];
            unsigned int ah3 = ash[wrow + gid + 8][tig + 4];
            unsigned int al0 = asl[wrow + gid][tig];
            unsigned int al1 = asl[wrow + gid + 8][tig];
            unsigned int al2 = asl[wrow + gid][tig + 4];
            unsigned int al3 = asl[wrow + gid + 8][tig + 4];
#pragma unroll
            for (int j = 0; j < 16; j++) {
                unsigned int bh0 = bsh[8 * j + gid][tig];
                unsigned int bh1 = bsh[8 * j + gid][tig + 4];
                unsigned int bl0 = bsl[8 * j + gid][tig];
                unsigned int bl1 = bsl[8 * j + gid][tig + 4];
                asm volatile(
                    "mma.sync.aligned.m16n8k16.row.col.f32.f16.f16.f32 "
                    "{%0,%1,%2,%3}, {%4,%5,%6,%7}, {%8,%9}, {%0,%1,%2,%3};"
                    : "+f"(acc[j][0]), "+f"(acc[j][1]),
                      "+f"(acc[j][2]), "+f"(acc[j][3])
                    : "r"(ah0), "r"(ah1), "r"(ah2), "r"(ah3), "r"(bh0), "r"(bh1));
                asm volatile(
                    "mma.sync.aligned.m16n8k16.row.col.f32.f16.f16.f32 "
                    "{%0,%1,%2,%3}, {%4,%5,%6,%7}, {%8,%9}, {%0,%1,%2,%3};"
                    : "+f"(acc[j][0]), "+f"(acc[j][1]),
                      "+f"(acc[j][2]), "+f"(acc[j][3])
                    : "r"(ah0), "r"(ah1), "r"(ah2), "r"(ah3), "r"(bl0), "r"(bl1));
                asm volatile(
                    "mma.sync.aligned.m16n8k16.row.col.f32.f16.f16.f32 "
                    "{%0,%1,%2,%3}, {%4,%5,%6,%7}, {%8,%9}, {%0,%1,%2,%3};"
                    : "+f"(acc[j][0]), "+f"(acc[j][1]),
                      "+f"(acc[j][2]), "+f"(acc[j][3])
                    : "r"(al0), "r"(al1), "r"(al2), "r"(al3), "r"(bh0), "r"(bh1));
            }
        }
        __syncthreads();
    }

    const int node0 = m0 + wrow + gid;
    const int node1 = node0 + 8;
#pragma unroll
    for (int j = 0; j < 16; j++) {
        int col = n0 + 8 * j + 2 * tig;
        if (OMODE == 0) {
            if (col < O) {   // aggregated half -> fp16
                if (node0 < NNODES)
                    *reinterpret_cast<__half2*>(g_zl + (size_t)node0 * O + col) =
                        __floats2half2_rn(acc[j][0], acc[j][1]);
                if (node1 < NNODES)
                    *reinterpret_cast<__half2*>(g_zl + (size_t)node1 * O + col) =
                        __floats2half2_rn(acc[j][2], acc[j][3]);
            } else {         // root half -> f32
                int c2 = col - O;
                if (node0 < NNODES)
                    *reinterpret_cast<float2*>(g_zr + (size_t)node0 * O + c2) =
                        make_float2(acc[j][0], acc[j][1]);
                if (node1 < NNODES)
                    *reinterpret_cast<float2*>(g_zr + (size_t)node1 * O + c2) =
                        make_float2(acc[j][2], acc[j][3]);
            }
        } else {
            float bx = bias[col], by = bias[col + 1];
            if (node0 < NNODES)
                *reinterpret_cast<float2*>(outp + (size_t)node0 * N2 + col) =
                    make_float2(acc[j][0] + bx, acc[j][1] + by);
            if (node1 < NNODES)
                *reinterpret_cast<float2*>(outp + (size_t)node1 * N2 + col) =
                    make_float2(acc[j][2] + bx, acc[j][3] + by);
        }
    }
}

// ======================= gather-add (fp16 z_l, unroll 8) =======================
// MODE 1 (O=128): fp16 split -> g_xh/g_xl [n][128].
// MODE 2 (O=64):  fp16 split -> RIGHT half of g_xh/g_xl [n][128], fp16 -> g_hfh.
template <int O, int MODE>
__global__ void gather_add_kernel(const float* __restrict__ b) {
    int warp = (blockIdx.x * blockDim.x + threadIdx.x) >> 5;
    int lane = threadIdx.x & 31;
    if (warp >= NNODES) return;
    int beg = g_rowptr[warp];
    int end = g_rowptr[warp + 1];
    float inv = g_inv[warp];

    if (O == 128) {
        float4 acc = make_float4(0.f, 0.f, 0.f, 0.f);
        int j = beg;
        for (; j + 7 < end; j += 8) {
            uint2 v[8];
#pragma unroll
            for (int u = 0; u < 8; u++) {
                int s = g_csr_src[j + u];
                v[u] = reinterpret_cast<const uint2*>(g_zl + (size_t)s * 128)[lane];
            }
#pragma unroll
            for (int u = 0; u < 8; u++) {
                float2 f0 = __half22float2(*reinterpret_cast<__half2*>(&v[u].x));
                float2 f1 = __half22float2(*reinterpret_cast<__half2*>(&v[u].y));
                acc.x += f0.x; acc.y += f0.y; acc.z += f1.x; acc.w += f1.y;
            }
        }
        for (; j < end; j++) {
            int s = g_csr_src[j];
            uint2 v = reinterpret_cast<const uint2*>(g_zl + (size_t)s * 128)[lane];
            float2 f0 = __half22float2(*reinterpret_cast<__half2*>(&v.x));
            float2 f1 = __half22float2(*reinterpret_cast<__half2*>(&v.y));
            acc.x += f0.x; acc.y += f0.y; acc.z += f1.x; acc.w += f1.y;
        }
        float4 zr = reinterpret_cast<const float4*>(g_zr + (size_t)warp * 128)[lane];
        float4 bb = reinterpret_cast<const float4*>(b)[lane];
        float4 res;
        res.x = acc.x * inv + zr.x + bb.x;
        res.y = acc.y * inv + zr.y + bb.y;
        res.z = acc.z * inv + zr.z + bb.z;
        res.w = acc.w * inv + zr.w + bb.w;
        unsigned short h[4], l[4];
        split_f16(res.x, h[0], l[0]);
        split_f16(res.y, h[1], l[1]);
        split_f16(res.z, h[2], l[2]);
        split_f16(res.w, h[3], l[3]);
        reinterpret_cast<uint2*>(g_xh + (size_t)warp * 128)[lane] =
            *reinterpret_cast<uint2*>(h);
        reinterpret_cast<uint2*>(g_xl + (size_t)warp * 128)[lane] =
            *reinterpret_cast<uint2*>(l);
    } else {
        float2 acc = make_float2(0.f, 0.f);
        int j = beg;
        for (; j + 7 < end; j += 8) {
            unsigned int v[8];
#pragma unroll
            for (int u = 0; u < 8; u++) {
                int s = g_csr_src[j + u];
                v[u] = reinterpret_cast<const unsigned int*>(g_zl + (size_t)s * 64)[lane];
            }
#pragma unroll
            for (int u = 0; u < 8; u++) {
                float2 f = __half22float2(*reinterpret_cast<__half2*>(&v[u]));
                acc.x += f.x; acc.y += f.y;
            }
        }
        for (; j < end; j++) {
            int s = g_csr_src[j];
            unsigned int v = reinterpret_cast<const unsigned int*>(g_zl + (size_t)s * 64)[lane];
            float2 f = __half22float2(*reinterpret_cast<__half2*>(&v));
            acc.x += f.x; acc.y += f.y;
        }
        float2 zr = reinterpret_cast<const float2*>(g_zr + (size_t)warp * 64)[lane];
        float2 bb = reinterpret_cast<const float2*>(b)[lane];
        float2 res;
        res.x = acc.x * inv + zr.x + bb.x;
        res.y = acc.y * inv + zr.y + bb.y;
        unsigned short h[2], l[2];
        split_f16(res.x, h[0], l[0]);
        split_f16(res.y, h[1], l[1]);
        reinterpret_cast<unsigned int*>(g_xh + (size_t)warp * 128 + 64)[lane] =
            *reinterpret_cast<unsigned int*>(h);
        reinterpret_cast<unsigned int*>(g_xl + (size_t)warp * 128 + 64)[lane] =
            *reinterpret_cast<unsigned int*>(l);
        *reinterpret_cast<__half2*>(g_hfh + (size_t)warp * 64 + lane * 2) =
            __floats2half2_rn(res.x, res.y);
    }
}

// gather-mean over g_hfh (fp16, 64-wide) -> fp16 split into LEFT half of A.
__global__ void gather_mean_split_kernel() {
    int warp = (blockIdx.x * blockDim.x + threadIdx.x) >> 5;
    int lane = threadIdx.x & 31;
    if (warp >= NNODES) return;
    int beg = g_rowptr[warp];
    int end = g_rowptr[warp + 1];
    float inv = g_inv[warp];

    float2 acc = make_float2(0.f, 0.f);
    int j = beg;
    for (; j + 7 < end; j += 8) {
        unsigned int v[8];
#pragma unroll
        for (int u = 0; u < 8; u++) {
            int s = g_csr_src[j + u];
            v[u] = reinterpret_cast<const unsigned int*>(g_hfh + (size_t)s * 64)[lane];
        }
#pragma unroll
        for (int u = 0; u < 8; u++) {
            float2 f = __half22float2(*reinterpret_cast<__half2*>(&v[u]));
            acc.x += f.x; acc.y += f.y;
        }
    }
    for (; j < end; j++) {
        int s = g_csr_src[j];
        unsigned int v = reinterpret_cast<const unsigned int*>(g_hfh + (size_t)s * 64)[lane];
        float2 f = __half22float2(*reinterpret_cast<__half2*>(&v));
        acc.x += f.x; acc.y += f.y;
    }
    acc.x *= inv; acc.y *= inv;
    unsigned short h[2], l[2];
    split_f16(acc.x, h[0], l[0]);
    split_f16(acc.y, h[1], l[1]);
    reinterpret_cast<unsigned int*>(g_xh + (size_t)warp * 128)[lane] =
        *reinterpret_cast<unsigned int*>(h);
    reinterpret_cast<unsigned int*>(g_xl + (size_t)warp * 128)[lane] =
        *reinterpret_cast<unsigned int*>(l);
}

// ======================= launch =======================
extern "C" void kernel_launch(void* const* d_in, const int* in_sizes, int n_in,
                              void* d_out, int out_size) {
    const float* x   = (const float*)d_in[0];
    const int*   ei  = (const int*)d_in[1];   // int32 (JAX x64 disabled)
    const float* Wl1 = (const float*)d_in[2];
    const float* b1  = (const float*)d_in[3];
    const float* Wr1 = (const float*)d_in[4];
    const float* Wl2 = (const float*)d_in[5];
    const float* b2  = (const float*)d_in[6];
    const float* Wr2 = (const float*)d_in[7];
    const float* Wl3 = (const float*)d_in[8];
    const float* b3  = (const float*)d_in[9];
    const float* Wr3 = (const float*)d_in[10];
    float* out = (float*)d_out;

    const int TB = 256;
    const int MT = NPAD / 128;                    // 391 M-tiles
    const int GW = (NNODES * 32 + TB - 1) / TB;   // gather: warp/node

    // Launch zero_deg FIRST so mma1 lands at launch #6 (ncu -s 5 -c 1 target).
    zero_deg_kernel<<<(NNODES + TB - 1) / TB, TB>>>();

    // Fork a side stream for the tensor-bound chain; rest of CSR build runs
    // concurrently on the main (capture) stream.
    cudaStream_t s1;
    cudaStreamCreate(&s1);
    cudaEvent_t evFork, evJoin;
    cudaEventCreateWithFlags(&evFork, cudaEventDisableTiming);
    cudaEventCreateWithFlags(&evJoin, cudaEventDisableTiming);

    cudaEventRecord(evFork, 0);
    cudaStreamWaitEvent(s1, evFork, 0);

    // ---- side stream: conversions + layer-1 GEMM ----
    conv_x_kernel<<<(NPAD * 128 / 8 + TB - 1) / TB, TB, 0, s1>>>(x);
    conv_w_kernel<128, 128, 1><<<(2 * 128 * 128 / 8 + TB - 1) / TB, TB, 0, s1>>>(Wl1, Wr1);
    conv_w_kernel<128, 64, 2><<<(2 * 64 * 128 / 8 + TB - 1) / TB, TB, 0, s1>>>(Wl2, Wr2);
    conv_wcat_kernel<64, 128, 3><<<(128 * 128 / 8 + TB - 1) / TB, TB, 0, s1>>>(Wl3, Wr3);
    mma_gemm_kernel<128, 256, 0, 1><<<dim3(MT, 2), 256, 0, s1>>>(nullptr, nullptr);
    cudaEventRecord(evJoin, s1);

    // ---- main stream: CSR build (concurrent) ----
    count_kernel<<<(NEDGES + TB - 1) / TB, TB>>>(ei);
    scan_kernel<<<1, SCAN_T>>>();
    fill_kernel<<<(NEDGES + TB - 1) / TB, TB>>>(ei);

    cudaStreamWaitEvent(0, evJoin, 0);   // join: gather needs CSR + z1

    // Layer 1 epilogue: h1 -> A[n][0..128)
    gather_add_kernel<128, 1><<<GW, TB>>>(b1);

    // Layer 2: I=128, N2=128
    mma_gemm_kernel<128, 128, 0, 2><<<MT, 256>>>(nullptr, nullptr);
    gather_add_kernel<64, 2><<<GW, TB>>>(b2);             // h2 -> A[n][64..128) + g_hfh

    // Layer 3: A = [mean(h2) | h2]; GEMM writes d_out + b3
    gather_mean_split_kernel<<<GW, TB>>>();               // mean -> A[n][0..64)
    mma_gemm_kernel<128, 128, 1, 3><<<MT, 256>>>(b3, out);
}